// round 4
// baseline (speedup 1.0000x reference)
#include <cuda_runtime.h>
#include <cuda_fp16.h>

#define BSZ 4
#define NSQ 16384
#define SSAMP 8
#define CPL 64
#define RESOL 128
#define HWSZ (RESOL * RESOL)
#define IND 192
#define NPTS (BSZ * NSQ)   // 65536

// ---------------- scratch (static device globals; no allocation) ----------------
__device__ __align__(16) float  g_planesf[(size_t)BSZ * 3 * HWSZ * CPL]; // fp32 channel-last
__device__ __align__(16) __half g_planesh[(size_t)BSZ * 3 * HWSZ * CPL]; // fp16 channel-last
__device__ __align__(16) __half g_feat_hi[(size_t)NPTS * IND];
__device__ __align__(16) __half g_feat_lo[(size_t)NPTS * IND];
__device__ __align__(16) float  g_offwt[(size_t)NPTS * 32];              // 24 off + 8 wt
__device__ __align__(16) __half g_auxw_hi[(size_t)NPTS * IND];
__device__ __align__(16) __half g_auxw_lo[(size_t)NPTS * IND];
__device__ float  g_wtsum[NPTS];
__device__ __align__(16) __half g_tmp_hi[(size_t)NPTS * IND];
__device__ __align__(16) __half g_tmp_lo[(size_t)NPTS * IND];
__device__ __align__(16) __half g_Wvh_hi[IND * IND];
__device__ __align__(16) __half g_Wvh_lo[IND * IND];
__device__ __align__(16) __half g_Wouth_hi[IND * IND];
__device__ __align__(16) __half g_Wouth_lo[IND * IND];
__device__ __align__(16) __half g_Wow_hi[32 * IND];                      // [Woff;Wwt] packed
__device__ __align__(16) __half g_Wow_lo[32 * IND];
__device__ float g_bow[32];

// ---------------- 1) transpose planes to channel-last (fp32 + fp16) ----------------
__global__ void transpose_planes(const float* __restrict__ pxz,
                                 const float* __restrict__ pxy,
                                 const float* __restrict__ pyz) {
    int p = blockIdx.z;
    int b = blockIdx.y;
    int yx0 = blockIdx.x * 32;
    const float* src = (p == 0 ? pxz : (p == 1 ? pxy : pyz)) + (size_t)b * CPL * HWSZ;
    float* dstf = g_planesf + (size_t)(b * 3 + p) * HWSZ * CPL;
    __half* dsth = g_planesh + (size_t)(b * 3 + p) * HWSZ * CPL;

    __shared__ float tile[CPL][33];
    int tx = threadIdx.x, ty = threadIdx.y;
#pragma unroll
    for (int cb = 0; cb < CPL; cb += 8) {
        int c = cb + ty;
        tile[c][tx] = src[(size_t)c * HWSZ + yx0 + tx];
    }
    __syncthreads();
    int t = ty * 32 + tx;
#pragma unroll
    for (int i = 0; i < 2; i++) {
        int e = i * 256 + t;
        int yxl = e >> 4;
        int c4 = (e & 15) * 4;
        float v0 = tile[c4 + 0][yxl], v1 = tile[c4 + 1][yxl];
        float v2 = tile[c4 + 2][yxl], v3 = tile[c4 + 3][yxl];
        size_t off = (size_t)(yx0 + yxl) * CPL + c4;
        *(float4*)(dstf + off) = make_float4(v0, v1, v2, v3);
        __half2 h0 = __floats2half2_rn(v0, v1);
        __half2 h1 = __floats2half2_rn(v2, v3);
        uint2 u;
        u.x = *(unsigned*)&h0;
        u.y = *(unsigned*)&h1;
        *(uint2*)(dsth + off) = u;
    }
}

// ---------------- 1b) split weights to fp16 hi/lo ----------------
__global__ void convert_w(const float* __restrict__ Wv, const float* __restrict__ Wout,
                          const float* __restrict__ Woff, const float* __restrict__ bo,
                          const float* __restrict__ Wwt, const float* __restrict__ bw) {
    int i = blockIdx.x * 256 + threadIdx.x;
    if (i < IND * IND) {
        float v = Wv[i];
        __half h = __float2half_rn(v);
        g_Wvh_hi[i] = h;
        g_Wvh_lo[i] = __float2half_rn(v - __half2float(h));
        float w = Wout[i];
        __half hw = __float2half_rn(w);
        g_Wouth_hi[i] = hw;
        g_Wouth_lo[i] = __float2half_rn(w - __half2float(hw));
    }
    if (i < 32 * IND) {
        int n = i / IND, k = i - n * IND;
        float v = (n < 24) ? Woff[n * IND + k] : Wwt[(n - 24) * IND + k];
        __half h = __float2half_rn(v);
        g_Wow_hi[i] = h;
        g_Wow_lo[i] = __float2half_rn(v - __half2float(h));
    }
    if (i < 32) g_bow[i] = (i < 24) ? bo[i] : bw[i - 24];
}

// ---------------- bilinear corner weights ----------------
__device__ __forceinline__ void bilerp_setup(float u, float v, int& i00, int& i01,
                                             int& i10, int& i11, float& w00, float& w01,
                                             float& w10, float& w11) {
    float x = __saturatef(u) * 127.0f;
    float y = __saturatef(v) * 127.0f;
    float xf = floorf(x), yf = floorf(y);
    int ix0 = (int)xf, iy0 = (int)yf;
    int ix1 = min(ix0 + 1, 127), iy1 = min(iy0 + 1, 127);
    float wx = x - xf, wy = y - yf;
    w00 = (1.0f - wx) * (1.0f - wy);
    w01 = wx * (1.0f - wy);
    w10 = (1.0f - wx) * wy;
    w11 = wx * wy;
    i00 = iy0 * RESOL + ix0; i01 = iy0 * RESOL + ix1;
    i10 = iy1 * RESOL + ix0; i11 = iy1 * RESOL + ix1;
}

__device__ __forceinline__ void store8_hilo(__half* dst_hi, __half* dst_lo,
                                            const float* acc) {
    uint4 phi, plo;
    __half2* hh = (__half2*)&phi;
    __half2* hl = (__half2*)&plo;
#pragma unroll
    for (int i = 0; i < 4; i++) {
        float a = acc[2 * i], b = acc[2 * i + 1];
        __half2 h = __floats2half2_rn(a, b);
        float2 hf = __half22float2(h);
        hh[i] = h;
        hl[i] = __floats2half2_rn(a - hf.x, b - hf.y);
    }
    *(uint4*)dst_hi = phi;
    *(uint4*)dst_lo = plo;
}

// ---------------- 2) sample features at query points (fp32 planes) ----------------
__global__ __launch_bounds__(256) void sample_query(const float* __restrict__ qp) {
    int gid = blockIdx.x * 256 + threadIdx.x;
    int pt = gid / 24, lane = gid - pt * 24;
    int c8 = lane * 8;
    int p = c8 >> 6, ch = c8 & 63;
    int b = pt >> 14;
    float px = qp[pt * 3 + 0], py = qp[pt * 3 + 1], pz = qp[pt * 3 + 2];
    float u = (p == 2) ? py : px;
    float v = (p == 1) ? py : pz;
    int i00, i01, i10, i11;
    float w00, w01, w10, w11;
    bilerp_setup(u, v, i00, i01, i10, i11, w00, w01, w10, w11);
    const float* base = g_planesf + (size_t)(b * 3 + p) * HWSZ * CPL + ch;
    float acc[8];
#pragma unroll
    for (int h = 0; h < 2; h++) {
        float4 f00 = *(const float4*)(base + (size_t)i00 * CPL + 4 * h);
        float4 f01 = *(const float4*)(base + (size_t)i01 * CPL + 4 * h);
        float4 f10 = *(const float4*)(base + (size_t)i10 * CPL + 4 * h);
        float4 f11 = *(const float4*)(base + (size_t)i11 * CPL + 4 * h);
        acc[4 * h + 0] = w00 * f00.x + w01 * f01.x + w10 * f10.x + w11 * f11.x;
        acc[4 * h + 1] = w00 * f00.y + w01 * f01.y + w10 * f10.y + w11 * f11.y;
        acc[4 * h + 2] = w00 * f00.z + w01 * f01.z + w10 * f10.z + w11 * f11.z;
        acc[4 * h + 3] = w00 * f00.w + w01 * f01.w + w10 * f10.w + w11 * f11.w;
    }
    size_t off = (size_t)pt * IND + c8;
    store8_hilo(g_feat_hi + off, g_feat_lo + off, acc);
}

// ---------------- MMA helpers ----------------
__device__ __forceinline__ void mma16816(float* c, const unsigned* a, const unsigned* b) {
    asm volatile(
        "mma.sync.aligned.m16n8k16.row.col.f32.f16.f16.f32 "
        "{%0,%1,%2,%3}, {%4,%5,%6,%7}, {%8,%9}, {%0,%1,%2,%3};\n"
        : "+f"(c[0]), "+f"(c[1]), "+f"(c[2]), "+f"(c[3])
        : "r"(a[0]), "r"(a[1]), "r"(a[2]), "r"(a[3]), "r"(b[0]), "r"(b[1]));
}
__device__ __forceinline__ void load_frag_a(const __half* p, unsigned* a) {
    a[0] = *(const unsigned*)p;
    a[1] = *(const unsigned*)(p + 8 * IND);
    a[2] = *(const unsigned*)(p + 8);
    a[3] = *(const unsigned*)(p + 8 * IND + 8);
}

// ---------------- 3) off+wt predictor via split-fp16 MMA ----------------
// M=NPTS, N=32, K=192. block 256 (8 warps x 32 rows), grid NPTS/256
__global__ __launch_bounds__(256) void predict_offwt_mma() {
    int tid = threadIdx.x, wid = tid >> 5, lane = tid & 31;
    int g = lane >> 2, t = lane & 3;
    int m_base = blockIdx.x * 256 + wid * 32;

    float c[2][4][4];
#pragma unroll
    for (int i = 0; i < 2; i++)
#pragma unroll
        for (int j = 0; j < 4; j++)
#pragma unroll
            for (int k = 0; k < 4; k++) c[i][j][k] = 0.0f;

    const __half* Aph = g_feat_hi + (size_t)(m_base + g) * IND + 2 * t;
    const __half* Apl = g_feat_lo + (size_t)(m_base + g) * IND + 2 * t;
    const __half* Bph = g_Wow_hi + (size_t)g * IND + 2 * t;
    const __half* Bpl = g_Wow_lo + (size_t)g * IND + 2 * t;

#pragma unroll 2
    for (int kt = 0; kt < 12; kt++) {
        int k0 = kt * 16;
        unsigned ah[2][4], al[2][4], bh[4][2], bl[4][2];
#pragma unroll
        for (int ms = 0; ms < 2; ms++) {
            load_frag_a(Aph + (size_t)ms * 16 * IND + k0, ah[ms]);
            load_frag_a(Apl + (size_t)ms * 16 * IND + k0, al[ms]);
        }
#pragma unroll
        for (int ns = 0; ns < 4; ns++) {
            const __half* ph = Bph + (size_t)ns * 8 * IND + k0;
            const __half* pl = Bpl + (size_t)ns * 8 * IND + k0;
            bh[ns][0] = *(const unsigned*)ph;
            bh[ns][1] = *(const unsigned*)(ph + 8);
            bl[ns][0] = *(const unsigned*)pl;
            bl[ns][1] = *(const unsigned*)(pl + 8);
        }
#pragma unroll
        for (int ms = 0; ms < 2; ms++)
#pragma unroll
            for (int ns = 0; ns < 4; ns++) {
                mma16816(c[ms][ns], ah[ms], bh[ns]);
                mma16816(c[ms][ns], ah[ms], bl[ns]);
                mma16816(c[ms][ns], al[ms], bh[ns]);
            }
    }

#pragma unroll
    for (int ms = 0; ms < 2; ms++) {
        int r0 = m_base + ms * 16 + g;
        int r1 = r0 + 8;
#pragma unroll
        for (int ns = 0; ns < 4; ns++) {
            int nc = ns * 8 + 2 * t;
            float b0 = g_bow[nc], b1 = g_bow[nc + 1];
            *(float2*)(g_offwt + (size_t)r0 * 32 + nc) =
                make_float2(c[ms][ns][0] + b0, c[ms][ns][1] + b1);
            *(float2*)(g_offwt + (size_t)r1 * 32 + nc) =
                make_float2(c[ms][ns][2] + b0, c[ms][ns][3] + b1);
        }
    }
}

// ---------------- 4) sample offset points, weighted-accumulate (fp16 planes) -----
__global__ __launch_bounds__(256) void sample_aux(const float* __restrict__ qp) {
    int gid = blockIdx.x * 256 + threadIdx.x;
    int pt = gid / 24, lane = gid - pt * 24;
    int c8 = lane * 8;
    int p = c8 >> 6, ch = c8 & 63;
    int b = pt >> 14;
    float px = qp[pt * 3 + 0], py = qp[pt * 3 + 1], pz = qp[pt * 3 + 2];
    const float* ow = g_offwt + (size_t)pt * 32;
    const __half* base = g_planesh + (size_t)(b * 3 + p) * HWSZ * CPL + ch;
    float acc[8] = {};
    float wts = 0.0f;
#pragma unroll
    for (int s = 0; s < SSAMP; s++) {
        float qx = px + ow[s * 3 + 0];
        float qy = py + ow[s * 3 + 1];
        float qz = pz + ow[s * 3 + 2];
        float wgt = ow[24 + s];
        float u = (p == 2) ? qy : qx;
        float v = (p == 1) ? qy : qz;
        int i00, i01, i10, i11;
        float w00, w01, w10, w11;
        bilerp_setup(u, v, i00, i01, i10, i11, w00, w01, w10, w11);
        w00 *= wgt; w01 *= wgt; w10 *= wgt; w11 *= wgt;
        uint4 q00 = *(const uint4*)(base + (size_t)i00 * CPL);
        uint4 q01 = *(const uint4*)(base + (size_t)i01 * CPL);
        uint4 q10 = *(const uint4*)(base + (size_t)i10 * CPL);
        uint4 q11 = *(const uint4*)(base + (size_t)i11 * CPL);
        const __half2* h00 = (const __half2*)&q00;
        const __half2* h01 = (const __half2*)&q01;
        const __half2* h10 = (const __half2*)&q10;
        const __half2* h11 = (const __half2*)&q11;
#pragma unroll
        for (int i = 0; i < 4; i++) {
            float2 f00 = __half22float2(h00[i]);
            float2 f01 = __half22float2(h01[i]);
            float2 f10 = __half22float2(h10[i]);
            float2 f11 = __half22float2(h11[i]);
            acc[2 * i + 0] += w00 * f00.x + w01 * f01.x + w10 * f10.x + w11 * f11.x;
            acc[2 * i + 1] += w00 * f00.y + w01 * f01.y + w10 * f10.y + w11 * f11.y;
        }
        wts += wgt;
    }
    size_t off = (size_t)pt * IND + c8;
    store8_hilo(g_auxw_hi + off, g_auxw_lo + off, acc);
    if (lane == 0) g_wtsum[pt] = wts;
}

// ---------------- 5) split-fp16 tensor-core GEMM (pre-split A) ----------------
// mode 0: A=auxw,  W=Wv,   C = acc + bias[n]*wtsum[m]            -> tmp hi/lo
// mode 1: A=tmp,   W=Wout, C = acc + bias[n] + (feat_hi+feat_lo) -> outF fp32
__global__ __launch_bounds__(256) void gemm_split(int mode,
                                                  const float* __restrict__ bias,
                                                  float* __restrict__ outF) {
    const __half* Ah = (mode == 0) ? g_auxw_hi : g_tmp_hi;
    const __half* Al = (mode == 0) ? g_auxw_lo : g_tmp_lo;
    const __half* Bh = (mode == 0) ? g_Wvh_hi : g_Wouth_hi;
    const __half* Bl = (mode == 0) ? g_Wvh_lo : g_Wouth_lo;
    int tid = threadIdx.x, wid = tid >> 5, lane = tid & 31;
    int g = lane >> 2, t = lane & 3;
    int m_base = blockIdx.x * 128 + (wid >> 1) * 32;
    int n_base = blockIdx.y * 64 + (wid & 1) * 32;

    float c[2][4][4];
#pragma unroll
    for (int i = 0; i < 2; i++)
#pragma unroll
        for (int j = 0; j < 4; j++)
#pragma unroll
            for (int k = 0; k < 4; k++) c[i][j][k] = 0.0f;

    const __half* Aph = Ah + (size_t)(m_base + g) * IND + 2 * t;
    const __half* Apl = Al + (size_t)(m_base + g) * IND + 2 * t;
    const __half* Bph = Bh + (size_t)(n_base + g) * IND + 2 * t;
    const __half* Bpl = Bl + (size_t)(n_base + g) * IND + 2 * t;

#pragma unroll 2
    for (int kt = 0; kt < 12; kt++) {
        int k0 = kt * 16;
        unsigned ah[2][4], al[2][4], bh[4][2], bl[4][2];
#pragma unroll
        for (int ms = 0; ms < 2; ms++) {
            load_frag_a(Aph + (size_t)ms * 16 * IND + k0, ah[ms]);
            load_frag_a(Apl + (size_t)ms * 16 * IND + k0, al[ms]);
        }
#pragma unroll
        for (int ns = 0; ns < 4; ns++) {
            const __half* ph = Bph + (size_t)ns * 8 * IND + k0;
            const __half* pl = Bpl + (size_t)ns * 8 * IND + k0;
            bh[ns][0] = *(const unsigned*)ph;
            bh[ns][1] = *(const unsigned*)(ph + 8);
            bl[ns][0] = *(const unsigned*)pl;
            bl[ns][1] = *(const unsigned*)(pl + 8);
        }
#pragma unroll
        for (int ms = 0; ms < 2; ms++)
#pragma unroll
            for (int ns = 0; ns < 4; ns++) {
                mma16816(c[ms][ns], ah[ms], bh[ns]);
                mma16816(c[ms][ns], ah[ms], bl[ns]);
                mma16816(c[ms][ns], al[ms], bh[ns]);
            }
    }

#pragma unroll
    for (int ms = 0; ms < 2; ms++) {
        int r0 = m_base + ms * 16 + g;
        int r1 = r0 + 8;
        float rs0 = 1.0f, rs1 = 1.0f;
        if (mode == 0) { rs0 = g_wtsum[r0]; rs1 = g_wtsum[r1]; }
#pragma unroll
        for (int ns = 0; ns < 4; ns++) {
            int nc = n_base + ns * 8 + 2 * t;
            float b0 = bias[nc], b1 = bias[nc + 1];
            float v00 = c[ms][ns][0] + b0 * rs0;
            float v01 = c[ms][ns][1] + b1 * rs0;
            float v10 = c[ms][ns][2] + b0 * rs1;
            float v11 = c[ms][ns][3] + b1 * rs1;
            if (mode == 0) {
                size_t o0 = (size_t)r0 * IND + nc;
                size_t o1 = (size_t)r1 * IND + nc;
                __half2 h0 = __floats2half2_rn(v00, v01);
                float2 h0f = __half22float2(h0);
                *(__half2*)(g_tmp_hi + o0) = h0;
                *(__half2*)(g_tmp_lo + o0) = __floats2half2_rn(v00 - h0f.x, v01 - h0f.y);
                __half2 h1 = __floats2half2_rn(v10, v11);
                float2 h1f = __half22float2(h1);
                *(__half2*)(g_tmp_hi + o1) = h1;
                *(__half2*)(g_tmp_lo + o1) = __floats2half2_rn(v10 - h1f.x, v11 - h1f.y);
            } else {
                size_t o0 = (size_t)r0 * IND + nc;
                size_t o1 = (size_t)r1 * IND + nc;
                float2 fh0 = __half22float2(*(const __half2*)(g_feat_hi + o0));
                float2 fl0 = __half22float2(*(const __half2*)(g_feat_lo + o0));
                float2 fh1 = __half22float2(*(const __half2*)(g_feat_hi + o1));
                float2 fl1 = __half22float2(*(const __half2*)(g_feat_lo + o1));
                *(float2*)(outF + o0) =
                    make_float2(v00 + fh0.x + fl0.x, v01 + fh0.y + fl0.y);
                *(float2*)(outF + o1) =
                    make_float2(v10 + fh1.x + fl1.x, v11 + fh1.y + fl1.y);
            }
        }
    }
}

// ---------------- launch ----------------
extern "C" void kernel_launch(void* const* d_in, const int* in_sizes, int n_in,
                              void* d_out, int out_size) {
    const float* qp    = (const float*)d_in[0];
    const float* fxz   = (const float*)d_in[1];
    const float* fxy   = (const float*)d_in[2];
    const float* fyz   = (const float*)d_in[3];
    const float* W_v   = (const float*)d_in[4];
    const float* b_v   = (const float*)d_in[5];
    const float* W_out = (const float*)d_in[6];
    const float* b_out = (const float*)d_in[7];
    const float* W_off = (const float*)d_in[8];
    const float* b_off = (const float*)d_in[9];
    const float* W_wt  = (const float*)d_in[10];
    const float* b_wt  = (const float*)d_in[11];
    float* out = (float*)d_out;

    transpose_planes<<<dim3(HWSZ / 32, BSZ, 3), dim3(32, 8)>>>(fxz, fxy, fyz);
    convert_w<<<(IND * IND + 255) / 256, 256>>>(W_v, W_out, W_off, b_off, W_wt, b_wt);
    sample_query<<<NPTS * 24 / 256, 256>>>(qp);
    predict_offwt_mma<<<NPTS / 256, 256>>>();
    sample_aux<<<NPTS * 24 / 256, 256>>>(qp);
    gemm_split<<<dim3(NPTS / 128, 3), 256>>>(0, b_v, nullptr);
    gemm_split<<<dim3(NPTS / 128, 3), 256>>>(1, b_out, out);
}

// round 5
// speedup vs baseline: 1.1765x; 1.1765x over previous
#include <cuda_runtime.h>
#include <cuda_fp16.h>

#define BSZ 4
#define NSQ 16384
#define SSAMP 8
#define CPL 64
#define RESOL 128
#define HWSZ (RESOL * RESOL)
#define IND 192
#define NPTS (BSZ * NSQ)   // 65536

// ---------------- scratch (static device globals; no allocation) ----------------
__device__ __align__(16) float  g_planesf[(size_t)BSZ * 3 * HWSZ * CPL]; // fp32 channel-last
__device__ __align__(16) __half g_planesh[(size_t)BSZ * 3 * HWSZ * CPL]; // fp16 channel-last
__device__ __align__(16) float  g_feat[(size_t)NPTS * IND];
__device__ __align__(16) float  g_offwt[(size_t)NPTS * 32];              // 24 off + 8 wt
__device__ __align__(16) float  g_auxw[(size_t)NPTS * IND];              // fp32
__device__ float  g_wtsum[NPTS];
__device__ __align__(16) float  g_tmp[(size_t)NPTS * IND];               // fp32
__device__ __align__(16) __half g_Wvh_hi[IND * IND];
__device__ __align__(16) __half g_Wvh_lo[IND * IND];
__device__ __align__(16) __half g_Wouth_hi[IND * IND];
__device__ __align__(16) __half g_Wouth_lo[IND * IND];
__device__ __align__(16) __half g_Wow_hi[32 * IND];                      // [Woff;Wwt] packed
__device__ __align__(16) __half g_Wow_lo[32 * IND];
__device__ float g_bow[32];

// ---------------- 1) transpose planes to channel-last (fp32 + fp16) ----------------
// grid (HW/32, B, 3), block (32, 8)
__global__ void transpose_planes(const float* __restrict__ pxz,
                                 const float* __restrict__ pxy,
                                 const float* __restrict__ pyz) {
    int p = blockIdx.z;
    int b = blockIdx.y;
    int yx0 = blockIdx.x * 32;
    const float* src = (p == 0 ? pxz : (p == 1 ? pxy : pyz)) + (size_t)b * CPL * HWSZ;
    float* dstf = g_planesf + (size_t)(b * 3 + p) * HWSZ * CPL;
    __half* dsth = g_planesh + (size_t)(b * 3 + p) * HWSZ * CPL;

    __shared__ float tile[CPL][33];
    int tx = threadIdx.x, ty = threadIdx.y;
#pragma unroll
    for (int cb = 0; cb < CPL; cb += 8) {
        int c = cb + ty;
        tile[c][tx] = src[(size_t)c * HWSZ + yx0 + tx];
    }
    __syncthreads();
    int t = ty * 32 + tx;
#pragma unroll
    for (int i = 0; i < 2; i++) {
        int e = i * 256 + t;          // 0..511
        int yxl = e >> 4;             // 0..31
        int c4 = (e & 15) * 4;        // 0..60
        float v0 = tile[c4 + 0][yxl], v1 = tile[c4 + 1][yxl];
        float v2 = tile[c4 + 2][yxl], v3 = tile[c4 + 3][yxl];
        size_t off = (size_t)(yx0 + yxl) * CPL + c4;
        *(float4*)(dstf + off) = make_float4(v0, v1, v2, v3);
        __half2 h0 = __floats2half2_rn(v0, v1);
        __half2 h1 = __floats2half2_rn(v2, v3);
        uint2 u;
        u.x = *(unsigned*)&h0;
        u.y = *(unsigned*)&h1;
        *(uint2*)(dsth + off) = u;
    }
}

// ---------------- 1b) split weights to fp16 hi/lo ----------------
__global__ void convert_w(const float* __restrict__ Wv, const float* __restrict__ Wout,
                          const float* __restrict__ Woff, const float* __restrict__ bo,
                          const float* __restrict__ Wwt, const float* __restrict__ bw) {
    int i = blockIdx.x * 256 + threadIdx.x;
    if (i < IND * IND) {
        float v = Wv[i];
        __half h = __float2half_rn(v);
        g_Wvh_hi[i] = h;
        g_Wvh_lo[i] = __float2half_rn(v - __half2float(h));
        float w = Wout[i];
        __half hw = __float2half_rn(w);
        g_Wouth_hi[i] = hw;
        g_Wouth_lo[i] = __float2half_rn(w - __half2float(hw));
    }
    if (i < 32 * IND) {
        int n = i / IND, k = i - n * IND;
        float v = (n < 24) ? Woff[n * IND + k] : Wwt[(n - 24) * IND + k];
        __half h = __float2half_rn(v);
        g_Wow_hi[i] = h;
        g_Wow_lo[i] = __float2half_rn(v - __half2float(h));
    }
    if (i < 32) g_bow[i] = (i < 24) ? bo[i] : bw[i - 24];
}

// ---------------- bilinear corner weights ----------------
__device__ __forceinline__ void bilerp_setup(float u, float v, int& i00, int& i01,
                                             int& i10, int& i11, float& w00, float& w01,
                                             float& w10, float& w11) {
    float x = __saturatef(u) * 127.0f;
    float y = __saturatef(v) * 127.0f;
    float xf = floorf(x), yf = floorf(y);
    int ix0 = (int)xf, iy0 = (int)yf;
    int ix1 = min(ix0 + 1, 127), iy1 = min(iy0 + 1, 127);
    float wx = x - xf, wy = y - yf;
    w00 = (1.0f - wx) * (1.0f - wy);
    w01 = wx * (1.0f - wy);
    w10 = (1.0f - wx) * wy;
    w11 = wx * wy;
    i00 = iy0 * RESOL + ix0; i01 = iy0 * RESOL + ix1;
    i10 = iy1 * RESOL + ix0; i11 = iy1 * RESOL + ix1;
}

// ---------------- 2) sample features at query points (fp32 planes) ----------------
// 24 lanes/pt, 8 ch/lane
__global__ __launch_bounds__(256) void sample_query(const float* __restrict__ qp) {
    int gid = blockIdx.x * 256 + threadIdx.x;
    int pt = gid / 24, lane = gid - pt * 24;
    int c8 = lane * 8;
    int p = c8 >> 6, ch = c8 & 63;
    int b = pt >> 14;
    float px = qp[pt * 3 + 0], py = qp[pt * 3 + 1], pz = qp[pt * 3 + 2];
    float u = (p == 2) ? py : px;
    float v = (p == 1) ? py : pz;
    int i00, i01, i10, i11;
    float w00, w01, w10, w11;
    bilerp_setup(u, v, i00, i01, i10, i11, w00, w01, w10, w11);
    const float* base = g_planesf + (size_t)(b * 3 + p) * HWSZ * CPL + ch;
    float acc[8];
#pragma unroll
    for (int h = 0; h < 2; h++) {
        float4 f00 = *(const float4*)(base + (size_t)i00 * CPL + 4 * h);
        float4 f01 = *(const float4*)(base + (size_t)i01 * CPL + 4 * h);
        float4 f10 = *(const float4*)(base + (size_t)i10 * CPL + 4 * h);
        float4 f11 = *(const float4*)(base + (size_t)i11 * CPL + 4 * h);
        acc[4 * h + 0] = w00 * f00.x + w01 * f01.x + w10 * f10.x + w11 * f11.x;
        acc[4 * h + 1] = w00 * f00.y + w01 * f01.y + w10 * f10.y + w11 * f11.y;
        acc[4 * h + 2] = w00 * f00.z + w01 * f01.z + w10 * f10.z + w11 * f11.z;
        acc[4 * h + 3] = w00 * f00.w + w01 * f01.w + w10 * f10.w + w11 * f11.w;
    }
    float4* o = (float4*)(g_feat + (size_t)pt * IND + c8);
    o[0] = make_float4(acc[0], acc[1], acc[2], acc[3]);
    o[1] = make_float4(acc[4], acc[5], acc[6], acc[7]);
}

// ---------------- MMA helpers ----------------
__device__ __forceinline__ void mma16816(float* c, const unsigned* a, const unsigned* b) {
    asm volatile(
        "mma.sync.aligned.m16n8k16.row.col.f32.f16.f16.f32 "
        "{%0,%1,%2,%3}, {%4,%5,%6,%7}, {%8,%9}, {%0,%1,%2,%3};\n"
        : "+f"(c[0]), "+f"(c[1]), "+f"(c[2]), "+f"(c[3])
        : "r"(a[0]), "r"(a[1]), "r"(a[2]), "r"(a[3]), "r"(b[0]), "r"(b[1]));
}
__device__ __forceinline__ void split2(float2 v, unsigned& hi, unsigned& lo) {
    __half2 h = __floats2half2_rn(v.x, v.y);
    float2 hf = __half22float2(h);
    __half2 l = __floats2half2_rn(v.x - hf.x, v.y - hf.y);
    hi = *(unsigned*)&h;
    lo = *(unsigned*)&l;
}
__device__ __forceinline__ void load_split_a(const float* p, unsigned* ah, unsigned* al) {
    split2(*(const float2*)(p), ah[0], al[0]);
    split2(*(const float2*)(p + 8 * IND), ah[1], al[1]);
    split2(*(const float2*)(p + 8), ah[2], al[2]);
    split2(*(const float2*)(p + 8 * IND + 8), ah[3], al[3]);
}

// ---------------- 3) off+wt predictor via split-fp16 MMA ----------------
// M=NPTS, N=32, K=192. block 256 (8 warps x 32 rows), grid NPTS/256
__global__ __launch_bounds__(256) void predict_offwt_mma() {
    int tid = threadIdx.x, wid = tid >> 5, lane = tid & 31;
    int g = lane >> 2, t = lane & 3;
    int m_base = blockIdx.x * 256 + wid * 32;

    float c[2][4][4];
#pragma unroll
    for (int i = 0; i < 2; i++)
#pragma unroll
        for (int j = 0; j < 4; j++)
#pragma unroll
            for (int k = 0; k < 4; k++) c[i][j][k] = 0.0f;

    const float* Ap = g_feat + (size_t)(m_base + g) * IND + 2 * t;
    const __half* Bph = g_Wow_hi + (size_t)g * IND + 2 * t;
    const __half* Bpl = g_Wow_lo + (size_t)g * IND + 2 * t;

#pragma unroll 2
    for (int kt = 0; kt < 12; kt++) {
        int k0 = kt * 16;
        unsigned ah[2][4], al[2][4], bh[4][2], bl[4][2];
#pragma unroll
        for (int ms = 0; ms < 2; ms++)
            load_split_a(Ap + (size_t)ms * 16 * IND + k0, ah[ms], al[ms]);
#pragma unroll
        for (int ns = 0; ns < 4; ns++) {
            const __half* ph = Bph + (size_t)ns * 8 * IND + k0;
            const __half* pl = Bpl + (size_t)ns * 8 * IND + k0;
            bh[ns][0] = *(const unsigned*)ph;
            bh[ns][1] = *(const unsigned*)(ph + 8);
            bl[ns][0] = *(const unsigned*)pl;
            bl[ns][1] = *(const unsigned*)(pl + 8);
        }
#pragma unroll
        for (int ms = 0; ms < 2; ms++)
#pragma unroll
            for (int ns = 0; ns < 4; ns++) {
                mma16816(c[ms][ns], ah[ms], bh[ns]);
                mma16816(c[ms][ns], ah[ms], bl[ns]);
                mma16816(c[ms][ns], al[ms], bh[ns]);
            }
    }

#pragma unroll
    for (int ms = 0; ms < 2; ms++) {
        int r0 = m_base + ms * 16 + g;
        int r1 = r0 + 8;
#pragma unroll
        for (int ns = 0; ns < 4; ns++) {
            int nc = ns * 8 + 2 * t;
            float b0 = g_bow[nc], b1 = g_bow[nc + 1];
            *(float2*)(g_offwt + (size_t)r0 * 32 + nc) =
                make_float2(c[ms][ns][0] + b0, c[ms][ns][1] + b1);
            *(float2*)(g_offwt + (size_t)r1 * 32 + nc) =
                make_float2(c[ms][ns][2] + b0, c[ms][ns][3] + b1);
        }
    }
}

// ---------------- 4) sample offset points, weighted-accumulate (fp16 planes) -----
__global__ __launch_bounds__(256) void sample_aux(const float* __restrict__ qp) {
    int gid = blockIdx.x * 256 + threadIdx.x;
    int pt = gid / 24, lane = gid - pt * 24;
    int c8 = lane * 8;
    int p = c8 >> 6, ch = c8 & 63;
    int b = pt >> 14;
    float px = qp[pt * 3 + 0], py = qp[pt * 3 + 1], pz = qp[pt * 3 + 2];
    const float* ow = g_offwt + (size_t)pt * 32;
    const __half* base = g_planesh + (size_t)(b * 3 + p) * HWSZ * CPL + ch;
    float acc[8] = {};
    float wts = 0.0f;
#pragma unroll
    for (int s = 0; s < SSAMP; s++) {
        float qx = px + ow[s * 3 + 0];
        float qy = py + ow[s * 3 + 1];
        float qz = pz + ow[s * 3 + 2];
        float wgt = ow[24 + s];
        float u = (p == 2) ? qy : qx;
        float v = (p == 1) ? qy : qz;
        int i00, i01, i10, i11;
        float w00, w01, w10, w11;
        bilerp_setup(u, v, i00, i01, i10, i11, w00, w01, w10, w11);
        w00 *= wgt; w01 *= wgt; w10 *= wgt; w11 *= wgt;
        uint4 q00 = *(const uint4*)(base + (size_t)i00 * CPL);
        uint4 q01 = *(const uint4*)(base + (size_t)i01 * CPL);
        uint4 q10 = *(const uint4*)(base + (size_t)i10 * CPL);
        uint4 q11 = *(const uint4*)(base + (size_t)i11 * CPL);
        const __half2* h00 = (const __half2*)&q00;
        const __half2* h01 = (const __half2*)&q01;
        const __half2* h10 = (const __half2*)&q10;
        const __half2* h11 = (const __half2*)&q11;
#pragma unroll
        for (int i = 0; i < 4; i++) {
            float2 f00 = __half22float2(h00[i]);
            float2 f01 = __half22float2(h01[i]);
            float2 f10 = __half22float2(h10[i]);
            float2 f11 = __half22float2(h11[i]);
            acc[2 * i + 0] += w00 * f00.x + w01 * f01.x + w10 * f10.x + w11 * f11.x;
            acc[2 * i + 1] += w00 * f00.y + w01 * f01.y + w10 * f10.y + w11 * f11.y;
        }
        wts += wgt;
    }
    float4* o = (float4*)(g_auxw + (size_t)pt * IND + c8);
    o[0] = make_float4(acc[0], acc[1], acc[2], acc[3]);
    o[1] = make_float4(acc[4], acc[5], acc[6], acc[7]);
    if (lane == 0) g_wtsum[pt] = wts;
}

// ---------------- 5) split-fp16 tensor-core GEMM (fp32-accurate) ----------------
// mode 0: A=g_auxw, W=Wv,  C = acc + bias[n]*wtsum[m]        -> g_tmp (fp32)
// mode 1: A=g_tmp,  W=Wout, C = acc + bias[n] + feat[m][n]   -> outF (fp32)
// grid (NPTS/128, 3), block 256 (8 warps: 4m x 2n, warp tile 32x32)
__global__ __launch_bounds__(256) void gemm_split(int mode,
                                                  const float* __restrict__ bias,
                                                  float* __restrict__ outF) {
    const float* A = (mode == 0) ? g_auxw : g_tmp;
    const __half* Bh = (mode == 0) ? g_Wvh_hi : g_Wouth_hi;
    const __half* Bl = (mode == 0) ? g_Wvh_lo : g_Wouth_lo;
    int tid = threadIdx.x, wid = tid >> 5, lane = tid & 31;
    int g = lane >> 2, t = lane & 3;
    int m_base = blockIdx.x * 128 + (wid >> 1) * 32;
    int n_base = blockIdx.y * 64 + (wid & 1) * 32;

    float c[2][4][4];
#pragma unroll
    for (int i = 0; i < 2; i++)
#pragma unroll
        for (int j = 0; j < 4; j++)
#pragma unroll
            for (int k = 0; k < 4; k++) c[i][j][k] = 0.0f;

    const float* Ap = A + (size_t)(m_base + g) * IND + 2 * t;
    const __half* Bph = Bh + (size_t)(n_base + g) * IND + 2 * t;
    const __half* Bpl = Bl + (size_t)(n_base + g) * IND + 2 * t;

#pragma unroll 2
    for (int kt = 0; kt < 12; kt++) {
        int k0 = kt * 16;
        unsigned ah[2][4], al[2][4], bh[4][2], bl[4][2];
#pragma unroll
        for (int ms = 0; ms < 2; ms++)
            load_split_a(Ap + (size_t)ms * 16 * IND + k0, ah[ms], al[ms]);
#pragma unroll
        for (int ns = 0; ns < 4; ns++) {
            const __half* ph = Bph + (size_t)ns * 8 * IND + k0;
            const __half* pl = Bpl + (size_t)ns * 8 * IND + k0;
            bh[ns][0] = *(const unsigned*)ph;
            bh[ns][1] = *(const unsigned*)(ph + 8);
            bl[ns][0] = *(const unsigned*)pl;
            bl[ns][1] = *(const unsigned*)(pl + 8);
        }
#pragma unroll
        for (int ms = 0; ms < 2; ms++)
#pragma unroll
            for (int ns = 0; ns < 4; ns++) {
                mma16816(c[ms][ns], ah[ms], bh[ns]);
                mma16816(c[ms][ns], ah[ms], bl[ns]);
                mma16816(c[ms][ns], al[ms], bh[ns]);
            }
    }

#pragma unroll
    for (int ms = 0; ms < 2; ms++) {
        int r0 = m_base + ms * 16 + g;
        int r1 = r0 + 8;
        float rs0 = 1.0f, rs1 = 1.0f;
        if (mode == 0) { rs0 = g_wtsum[r0]; rs1 = g_wtsum[r1]; }
#pragma unroll
        for (int ns = 0; ns < 4; ns++) {
            int nc = n_base + ns * 8 + 2 * t;
            float b0 = bias[nc], b1 = bias[nc + 1];
            float v00 = c[ms][ns][0] + b0 * rs0;
            float v01 = c[ms][ns][1] + b1 * rs0;
            float v10 = c[ms][ns][2] + b0 * rs1;
            float v11 = c[ms][ns][3] + b1 * rs1;
            if (mode == 0) {
                *(float2*)(g_tmp + (size_t)r0 * IND + nc) = make_float2(v00, v01);
                *(float2*)(g_tmp + (size_t)r1 * IND + nc) = make_float2(v10, v11);
            } else {
                float2 f0 = *(const float2*)(g_feat + (size_t)r0 * IND + nc);
                float2 f1 = *(const float2*)(g_feat + (size_t)r1 * IND + nc);
                *(float2*)(outF + (size_t)r0 * IND + nc) = make_float2(v00 + f0.x, v01 + f0.y);
                *(float2*)(outF + (size_t)r1 * IND + nc) = make_float2(v10 + f1.x, v11 + f1.y);
            }
        }
    }
}

// ---------------- launch ----------------
extern "C" void kernel_launch(void* const* d_in, const int* in_sizes, int n_in,
                              void* d_out, int out_size) {
    const float* qp    = (const float*)d_in[0];
    const float* fxz   = (const float*)d_in[1];
    const float* fxy   = (const float*)d_in[2];
    const float* fyz   = (const float*)d_in[3];
    const float* W_v   = (const float*)d_in[4];
    const float* b_v   = (const float*)d_in[5];
    const float* W_out = (const float*)d_in[6];
    const float* b_out = (const float*)d_in[7];
    const float* W_off = (const float*)d_in[8];
    const float* b_off = (const float*)d_in[9];
    const float* W_wt  = (const float*)d_in[10];
    const float* b_wt  = (const float*)d_in[11];
    float* out = (float*)d_out;

    transpose_planes<<<dim3(HWSZ / 32, BSZ, 3), dim3(32, 8)>>>(fxz, fxy, fyz);
    convert_w<<<(IND * IND + 255) / 256, 256>>>(W_v, W_out, W_off, b_off, W_wt, b_wt);
    sample_query<<<NPTS * 24 / 256, 256>>>(qp);
    predict_offwt_mma<<<NPTS / 256, 256>>>();
    sample_aux<<<NPTS * 24 / 256, 256>>>(qp);
    gemm_split<<<dim3(NPTS / 128, 3), 256>>>(0, b_v, nullptr);
    gemm_split<<<dim3(NPTS / 128, 3), 256>>>(1, b_out, out);
}

// round 6
// speedup vs baseline: 1.4759x; 1.2546x over previous
#include <cuda_runtime.h>
#include <cuda_fp16.h>

#define BSZ 4
#define NSQ 16384
#define SSAMP 8
#define CPL 64
#define RESOL 128
#define HWSZ (RESOL * RESOL)
#define IND 192
#define NPTS (BSZ * NSQ)   // 65536

// ---------------- scratch (static device globals; no allocation) ----------------
__device__ __align__(16) float  g_planesf[(size_t)BSZ * 3 * HWSZ * CPL]; // fp32 channel-last
__device__ __align__(16) __half g_planesh[(size_t)BSZ * 3 * HWSZ * CPL]; // fp16 channel-last
__device__ __align__(16) float  g_feat[(size_t)NPTS * IND];
__device__ __align__(16) float  g_offwt[(size_t)NPTS * 32];              // 24 off + 8 wt
__device__ __align__(16) float  g_auxw[(size_t)NPTS * IND];              // fp32
__device__ float  g_wtsum[NPTS];
__device__ __align__(16) __half g_Wc_hi[IND * IND];                      // Wout@Wv split
__device__ __align__(16) __half g_Wc_lo[IND * IND];
__device__ float g_bvout[IND];                                           // Wout@b_v
__device__ __align__(16) __half g_Wow_hi[32 * IND];                      // [Woff;Wwt] packed
__device__ __align__(16) __half g_Wow_lo[32 * IND];
__device__ float g_bow[32];

// ---------------- 1) transpose planes to channel-last (fp32 + fp16) ----------------
// grid (HW/32, B, 3), block (32, 8)
__global__ void transpose_planes(const float* __restrict__ pxz,
                                 const float* __restrict__ pxy,
                                 const float* __restrict__ pyz) {
    int p = blockIdx.z;
    int b = blockIdx.y;
    int yx0 = blockIdx.x * 32;
    const float* src = (p == 0 ? pxz : (p == 1 ? pxy : pyz)) + (size_t)b * CPL * HWSZ;
    float* dstf = g_planesf + (size_t)(b * 3 + p) * HWSZ * CPL;
    __half* dsth = g_planesh + (size_t)(b * 3 + p) * HWSZ * CPL;

    __shared__ float tile[CPL][33];
    int tx = threadIdx.x, ty = threadIdx.y;
#pragma unroll
    for (int cb = 0; cb < CPL; cb += 8) {
        int c = cb + ty;
        tile[c][tx] = src[(size_t)c * HWSZ + yx0 + tx];
    }
    __syncthreads();
    int t = ty * 32 + tx;
#pragma unroll
    for (int i = 0; i < 2; i++) {
        int e = i * 256 + t;          // 0..511
        int yxl = e >> 4;             // 0..31
        int c4 = (e & 15) * 4;        // 0..60
        float v0 = tile[c4 + 0][yxl], v1 = tile[c4 + 1][yxl];
        float v2 = tile[c4 + 2][yxl], v3 = tile[c4 + 3][yxl];
        size_t off = (size_t)(yx0 + yxl) * CPL + c4;
        *(float4*)(dstf + off) = make_float4(v0, v1, v2, v3);
        __half2 h0 = __floats2half2_rn(v0, v1);
        __half2 h1 = __floats2half2_rn(v2, v3);
        uint2 u;
        u.x = *(unsigned*)&h0;
        u.y = *(unsigned*)&h1;
        *(uint2*)(dsth + off) = u;
    }
}

// ---------------- 1b) split off/wt weights; bvout ----------------
__global__ void convert_w(const float* __restrict__ Woff, const float* __restrict__ bo,
                          const float* __restrict__ Wwt, const float* __restrict__ bw,
                          const float* __restrict__ Wout, const float* __restrict__ bv) {
    int i = blockIdx.x * 256 + threadIdx.x;
    if (i < 32 * IND) {
        int n = i / IND, k = i - n * IND;
        float v = (n < 24) ? Woff[n * IND + k] : Wwt[(n - 24) * IND + k];
        __half h = __float2half_rn(v);
        g_Wow_hi[i] = h;
        g_Wow_lo[i] = __float2half_rn(v - __half2float(h));
    }
    if (i < 32) g_bow[i] = (i < 24) ? bo[i] : bw[i - 24];
    if (i < IND) {
        float s = 0.0f;
        for (int n = 0; n < IND; n++) s += Wout[i * IND + n] * bv[n];
        g_bvout[i] = s;
    }
}

// ---------------- 1c) W_comb = Wout @ Wv, split hi/lo ----------------
// grid IND (m), block IND (k)
__global__ void make_wcomb(const float* __restrict__ Wout, const float* __restrict__ Wv) {
    __shared__ float wrow[IND];
    int m = blockIdx.x, k = threadIdx.x;
    wrow[k] = Wout[m * IND + k];
    __syncthreads();
    float s = 0.0f;
#pragma unroll 4
    for (int n = 0; n < IND; n++) s += wrow[n] * Wv[n * IND + k];
    __half h = __float2half_rn(s);
    g_Wc_hi[m * IND + k] = h;
    g_Wc_lo[m * IND + k] = __float2half_rn(s - __half2float(h));
}

// ---------------- bilinear corner weights ----------------
__device__ __forceinline__ void bilerp_setup(float u, float v, int& i00, int& i01,
                                             int& i10, int& i11, float& w00, float& w01,
                                             float& w10, float& w11) {
    float x = __saturatef(u) * 127.0f;
    float y = __saturatef(v) * 127.0f;
    float xf = floorf(x), yf = floorf(y);
    int ix0 = (int)xf, iy0 = (int)yf;
    int ix1 = min(ix0 + 1, 127), iy1 = min(iy0 + 1, 127);
    float wx = x - xf, wy = y - yf;
    w00 = (1.0f - wx) * (1.0f - wy);
    w01 = wx * (1.0f - wy);
    w10 = (1.0f - wx) * wy;
    w11 = wx * wy;
    i00 = iy0 * RESOL + ix0; i01 = iy0 * RESOL + ix1;
    i10 = iy1 * RESOL + ix0; i11 = iy1 * RESOL + ix1;
}

// ---------------- 2) sample features at query points (fp32 planes) ----------------
// 24 lanes/pt, 8 ch/lane
__global__ __launch_bounds__(256) void sample_query(const float* __restrict__ qp) {
    int gid = blockIdx.x * 256 + threadIdx.x;
    int pt = gid / 24, lane = gid - pt * 24;
    int c8 = lane * 8;
    int p = c8 >> 6, ch = c8 & 63;
    int b = pt >> 14;
    float px = qp[pt * 3 + 0], py = qp[pt * 3 + 1], pz = qp[pt * 3 + 2];
    float u = (p == 2) ? py : px;
    float v = (p == 1) ? py : pz;
    int i00, i01, i10, i11;
    float w00, w01, w10, w11;
    bilerp_setup(u, v, i00, i01, i10, i11, w00, w01, w10, w11);
    const float* base = g_planesf + (size_t)(b * 3 + p) * HWSZ * CPL + ch;
    float acc[8];
#pragma unroll
    for (int h = 0; h < 2; h++) {
        float4 f00 = *(const float4*)(base + (size_t)i00 * CPL + 4 * h);
        float4 f01 = *(const float4*)(base + (size_t)i01 * CPL + 4 * h);
        float4 f10 = *(const float4*)(base + (size_t)i10 * CPL + 4 * h);
        float4 f11 = *(const float4*)(base + (size_t)i11 * CPL + 4 * h);
        acc[4 * h + 0] = w00 * f00.x + w01 * f01.x + w10 * f10.x + w11 * f11.x;
        acc[4 * h + 1] = w00 * f00.y + w01 * f01.y + w10 * f10.y + w11 * f11.y;
        acc[4 * h + 2] = w00 * f00.z + w01 * f01.z + w10 * f10.z + w11 * f11.z;
        acc[4 * h + 3] = w00 * f00.w + w01 * f01.w + w10 * f10.w + w11 * f11.w;
    }
    float4* o = (float4*)(g_feat + (size_t)pt * IND + c8);
    o[0] = make_float4(acc[0], acc[1], acc[2], acc[3]);
    o[1] = make_float4(acc[4], acc[5], acc[6], acc[7]);
}

// ---------------- MMA helpers ----------------
__device__ __forceinline__ void mma16816(float* c, const unsigned* a, const unsigned* b) {
    asm volatile(
        "mma.sync.aligned.m16n8k16.row.col.f32.f16.f16.f32 "
        "{%0,%1,%2,%3}, {%4,%5,%6,%7}, {%8,%9}, {%0,%1,%2,%3};\n"
        : "+f"(c[0]), "+f"(c[1]), "+f"(c[2]), "+f"(c[3])
        : "r"(a[0]), "r"(a[1]), "r"(a[2]), "r"(a[3]), "r"(b[0]), "r"(b[1]));
}
__device__ __forceinline__ void split2(float2 v, unsigned& hi, unsigned& lo) {
    __half2 h = __floats2half2_rn(v.x, v.y);
    float2 hf = __half22float2(h);
    __half2 l = __floats2half2_rn(v.x - hf.x, v.y - hf.y);
    hi = *(unsigned*)&h;
    lo = *(unsigned*)&l;
}
__device__ __forceinline__ void load_split_a(const float* p, unsigned* ah, unsigned* al) {
    split2(*(const float2*)(p), ah[0], al[0]);
    split2(*(const float2*)(p + 8 * IND), ah[1], al[1]);
    split2(*(const float2*)(p + 8), ah[2], al[2]);
    split2(*(const float2*)(p + 8 * IND + 8), ah[3], al[3]);
}

// ---------------- 3) off+wt predictor via split-fp16 MMA ----------------
// M=NPTS, N=32, K=192. block 256 (8 warps x 32 rows), grid NPTS/256
__global__ __launch_bounds__(256) void predict_offwt_mma() {
    int tid = threadIdx.x, wid = tid >> 5, lane = tid & 31;
    int g = lane >> 2, t = lane & 3;
    int m_base = blockIdx.x * 256 + wid * 32;

    float c[2][4][4];
#pragma unroll
    for (int i = 0; i < 2; i++)
#pragma unroll
        for (int j = 0; j < 4; j++)
#pragma unroll
            for (int k = 0; k < 4; k++) c[i][j][k] = 0.0f;

    const float* Ap = g_feat + (size_t)(m_base + g) * IND + 2 * t;
    const __half* Bph = g_Wow_hi + (size_t)g * IND + 2 * t;
    const __half* Bpl = g_Wow_lo + (size_t)g * IND + 2 * t;

#pragma unroll 2
    for (int kt = 0; kt < 12; kt++) {
        int k0 = kt * 16;
        unsigned ah[2][4], al[2][4], bh[4][2], bl[4][2];
#pragma unroll
        for (int ms = 0; ms < 2; ms++)
            load_split_a(Ap + (size_t)ms * 16 * IND + k0, ah[ms], al[ms]);
#pragma unroll
        for (int ns = 0; ns < 4; ns++) {
            const __half* ph = Bph + (size_t)ns * 8 * IND + k0;
            const __half* pl = Bpl + (size_t)ns * 8 * IND + k0;
            bh[ns][0] = *(const unsigned*)ph;
            bh[ns][1] = *(const unsigned*)(ph + 8);
            bl[ns][0] = *(const unsigned*)pl;
            bl[ns][1] = *(const unsigned*)(pl + 8);
        }
#pragma unroll
        for (int ms = 0; ms < 2; ms++)
#pragma unroll
            for (int ns = 0; ns < 4; ns++) {
                mma16816(c[ms][ns], ah[ms], bh[ns]);
                mma16816(c[ms][ns], ah[ms], bl[ns]);
                mma16816(c[ms][ns], al[ms], bh[ns]);
            }
    }

#pragma unroll
    for (int ms = 0; ms < 2; ms++) {
        int r0 = m_base + ms * 16 + g;
        int r1 = r0 + 8;
#pragma unroll
        for (int ns = 0; ns < 4; ns++) {
            int nc = ns * 8 + 2 * t;
            float b0 = g_bow[nc], b1 = g_bow[nc + 1];
            *(float2*)(g_offwt + (size_t)r0 * 32 + nc) =
                make_float2(c[ms][ns][0] + b0, c[ms][ns][1] + b1);
            *(float2*)(g_offwt + (size_t)r1 * 32 + nc) =
                make_float2(c[ms][ns][2] + b0, c[ms][ns][3] + b1);
        }
    }
}

// ---------------- 4) sample offset points, weighted-accumulate (fp16 planes) -----
__global__ __launch_bounds__(256) void sample_aux(const float* __restrict__ qp) {
    int gid = blockIdx.x * 256 + threadIdx.x;
    int pt = gid / 24, lane = gid - pt * 24;
    int c8 = lane * 8;
    int p = c8 >> 6, ch = c8 & 63;
    int b = pt >> 14;
    float px = qp[pt * 3 + 0], py = qp[pt * 3 + 1], pz = qp[pt * 3 + 2];
    const float* ow = g_offwt + (size_t)pt * 32;
    const __half* base = g_planesh + (size_t)(b * 3 + p) * HWSZ * CPL + ch;
    float acc[8] = {};
    float wts = 0.0f;
#pragma unroll
    for (int s = 0; s < SSAMP; s++) {
        float qx = px + ow[s * 3 + 0];
        float qy = py + ow[s * 3 + 1];
        float qz = pz + ow[s * 3 + 2];
        float wgt = ow[24 + s];
        float u = (p == 2) ? qy : qx;
        float v = (p == 1) ? qy : qz;
        int i00, i01, i10, i11;
        float w00, w01, w10, w11;
        bilerp_setup(u, v, i00, i01, i10, i11, w00, w01, w10, w11);
        w00 *= wgt; w01 *= wgt; w10 *= wgt; w11 *= wgt;
        uint4 q00 = *(const uint4*)(base + (size_t)i00 * CPL);
        uint4 q01 = *(const uint4*)(base + (size_t)i01 * CPL);
        uint4 q10 = *(const uint4*)(base + (size_t)i10 * CPL);
        uint4 q11 = *(const uint4*)(base + (size_t)i11 * CPL);
        const __half2* h00 = (const __half2*)&q00;
        const __half2* h01 = (const __half2*)&q01;
        const __half2* h10 = (const __half2*)&q10;
        const __half2* h11 = (const __half2*)&q11;
#pragma unroll
        for (int i = 0; i < 4; i++) {
            float2 f00 = __half22float2(h00[i]);
            float2 f01 = __half22float2(h01[i]);
            float2 f10 = __half22float2(h10[i]);
            float2 f11 = __half22float2(h11[i]);
            acc[2 * i + 0] += w00 * f00.x + w01 * f01.x + w10 * f10.x + w11 * f11.x;
            acc[2 * i + 1] += w00 * f00.y + w01 * f01.y + w10 * f10.y + w11 * f11.y;
        }
        wts += wgt;
    }
    float4* o = (float4*)(g_auxw + (size_t)pt * IND + c8);
    o[0] = make_float4(acc[0], acc[1], acc[2], acc[3]);
    o[1] = make_float4(acc[4], acc[5], acc[6], acc[7]);
    if (lane == 0) g_wtsum[pt] = wts;
}

// ---------------- 5) single fused GEMM: out = auxw@Wc^T + wts*bvout + bout + feat
// grid (NPTS/128, 3), block 256 (8 warps: 4m x 2n, warp tile 32x32)
__global__ __launch_bounds__(256) void gemm_comb(const float* __restrict__ bout,
                                                 float* __restrict__ outF) {
    int tid = threadIdx.x, wid = tid >> 5, lane = tid & 31;
    int g = lane >> 2, t = lane & 3;
    int m_base = blockIdx.x * 128 + (wid >> 1) * 32;
    int n_base = blockIdx.y * 64 + (wid & 1) * 32;

    float c[2][4][4];
#pragma unroll
    for (int i = 0; i < 2; i++)
#pragma unroll
        for (int j = 0; j < 4; j++)
#pragma unroll
            for (int k = 0; k < 4; k++) c[i][j][k] = 0.0f;

    const float* Ap = g_auxw + (size_t)(m_base + g) * IND + 2 * t;
    const __half* Bph = g_Wc_hi + (size_t)(n_base + g) * IND + 2 * t;
    const __half* Bpl = g_Wc_lo + (size_t)(n_base + g) * IND + 2 * t;

#pragma unroll 2
    for (int kt = 0; kt < 12; kt++) {
        int k0 = kt * 16;
        unsigned ah[2][4], al[2][4], bh[4][2], bl[4][2];
#pragma unroll
        for (int ms = 0; ms < 2; ms++)
            load_split_a(Ap + (size_t)ms * 16 * IND + k0, ah[ms], al[ms]);
#pragma unroll
        for (int ns = 0; ns < 4; ns++) {
            const __half* ph = Bph + (size_t)ns * 8 * IND + k0;
            const __half* pl = Bpl + (size_t)ns * 8 * IND + k0;
            bh[ns][0] = *(const unsigned*)ph;
            bh[ns][1] = *(const unsigned*)(ph + 8);
            bl[ns][0] = *(const unsigned*)pl;
            bl[ns][1] = *(const unsigned*)(pl + 8);
        }
#pragma unroll
        for (int ms = 0; ms < 2; ms++)
#pragma unroll
            for (int ns = 0; ns < 4; ns++) {
                mma16816(c[ms][ns], ah[ms], bh[ns]);
                mma16816(c[ms][ns], ah[ms], bl[ns]);
                mma16816(c[ms][ns], al[ms], bh[ns]);
            }
    }

#pragma unroll
    for (int ms = 0; ms < 2; ms++) {
        int r0 = m_base + ms * 16 + g;
        int r1 = r0 + 8;
        float rs0 = g_wtsum[r0], rs1 = g_wtsum[r1];
#pragma unroll
        for (int ns = 0; ns < 4; ns++) {
            int nc = n_base + ns * 8 + 2 * t;
            float bo0 = bout[nc], bo1 = bout[nc + 1];
            float bv0 = g_bvout[nc], bv1 = g_bvout[nc + 1];
            size_t o0 = (size_t)r0 * IND + nc;
            size_t o1 = (size_t)r1 * IND + nc;
            float2 f0 = *(const float2*)(g_feat + o0);
            float2 f1 = *(const float2*)(g_feat + o1);
            *(float2*)(outF + o0) = make_float2(
                c[ms][ns][0] + bv0 * rs0 + bo0 + f0.x,
                c[ms][ns][1] + bv1 * rs0 + bo1 + f0.y);
            *(float2*)(outF + o1) = make_float2(
                c[ms][ns][2] + bv0 * rs1 + bo0 + f1.x,
                c[ms][ns][3] + bv1 * rs1 + bo1 + f1.y);
        }
    }
}

// ---------------- launch ----------------
extern "C" void kernel_launch(void* const* d_in, const int* in_sizes, int n_in,
                              void* d_out, int out_size) {
    const float* qp    = (const float*)d_in[0];
    const float* fxz   = (const float*)d_in[1];
    const float* fxy   = (const float*)d_in[2];
    const float* fyz   = (const float*)d_in[3];
    const float* W_v   = (const float*)d_in[4];
    const float* b_v   = (const float*)d_in[5];
    const float* W_out = (const float*)d_in[6];
    const float* b_out = (const float*)d_in[7];
    const float* W_off = (const float*)d_in[8];
    const float* b_off = (const float*)d_in[9];
    const float* W_wt  = (const float*)d_in[10];
    const float* b_wt  = (const float*)d_in[11];
    float* out = (float*)d_out;

    transpose_planes<<<dim3(HWSZ / 32, BSZ, 3), dim3(32, 8)>>>(fxz, fxy, fyz);
    convert_w<<<(32 * IND + 255) / 256, 256>>>(W_off, b_off, W_wt, b_wt, W_out, b_v);
    make_wcomb<<<IND, IND>>>(W_out, W_v);
    sample_query<<<NPTS * 24 / 256, 256>>>(qp);
    predict_offwt_mma<<<NPTS / 256, 256>>>();
    sample_aux<<<NPTS * 24 / 256, 256>>>(qp);
    gemm_comb<<<dim3(NPTS / 128, 3), 256>>>(b_out, out);
}

// round 7
// speedup vs baseline: 1.6387x; 1.1103x over previous
#include <cuda_runtime.h>
#include <cuda_fp16.h>

#define BSZ 4
#define NSQ 16384
#define SSAMP 8
#define CPL 64
#define RESOL 128
#define HWSZ (RESOL * RESOL)
#define IND 192
#define NPTS (BSZ * NSQ)   // 65536

// ---------------- scratch (static device globals; no allocation) ----------------
__device__ __align__(16) float  g_planesf[(size_t)BSZ * 3 * HWSZ * CPL]; // fp32 channel-last
__device__ __align__(16) __half g_planesh[(size_t)BSZ * 3 * HWSZ * CPL]; // fp16 channel-last
__device__ __align__(16) float  g_feat[(size_t)NPTS * IND];
__device__ __align__(16) float  g_offwt[(size_t)NPTS * 32];              // 24 off + 8 wt
__device__ __align__(16) float  g_auxw[(size_t)NPTS * IND];              // fp32
__device__ float  g_wtsum[NPTS];
__device__ __align__(16) __half g_Wc_hi[IND * IND];                      // Wout@Wv split
__device__ __align__(16) __half g_Wc_lo[IND * IND];
__device__ float g_bvout[IND];                                           // Wout@b_v
__device__ __align__(16) __half g_Wow_hi[32 * IND];                      // [Woff;Wwt] packed
__device__ __align__(16) __half g_Wow_lo[32 * IND];
__device__ float g_bow[32];

// ---------------- 1) transpose planes to channel-last (fp32 + fp16) ----------------
// grid (HW/128, B, 3), block 256
__global__ __launch_bounds__(256) void transpose_planes(const float* __restrict__ pxz,
                                                        const float* __restrict__ pxy,
                                                        const float* __restrict__ pyz) {
    int p = blockIdx.z;
    int b = blockIdx.y;
    int yx0 = blockIdx.x * 128;
    const float* src = (p == 0 ? pxz : (p == 1 ? pxy : pyz)) + (size_t)b * CPL * HWSZ;
    float* dstf = g_planesf + (size_t)(b * 3 + p) * HWSZ * CPL;
    __half* dsth = g_planesh + (size_t)(b * 3 + p) * HWSZ * CPL;

    __shared__ float tile[CPL][132];   // 132-pad: STS.128 aligned
    int t = threadIdx.x;
    int tx = t & 31, ty = t >> 5;      // 32 x 8
#pragma unroll
    for (int cb = 0; cb < CPL; cb += 8) {
        int c = cb + ty;
        float4 v = *(const float4*)(src + (size_t)c * HWSZ + yx0 + tx * 4);
        *(float4*)(&tile[c][tx * 4]) = v;
    }
    __syncthreads();
    // fp32 out: tasks (c8 0..7) x (yxl 0..127); lane-consecutive yxl -> conflict-free LDS,
    // 32B-consecutive stores per lane.
#pragma unroll
    for (int i = 0; i < 4; i++) {
        int e = i * 256 + t;
        int c8 = e >> 7, yxl = e & 127;
        float v[8];
#pragma unroll
        for (int j = 0; j < 8; j++) v[j] = tile[c8 * 8 + j][yxl];
        size_t off = (size_t)(yx0 + yxl) * CPL + c8 * 8;
        *(float4*)(dstf + off) = make_float4(v[0], v[1], v[2], v[3]);
        *(float4*)(dstf + off + 4) = make_float4(v[4], v[5], v[6], v[7]);
    }
    // fp16 out: tasks (c16 0..3) x (yxl 0..127); 32B-consecutive per lane.
#pragma unroll
    for (int i = 0; i < 2; i++) {
        int e = i * 256 + t;
        int c16 = e >> 7, yxl = e & 127;
        uint4 u0, u1;
        __half2* hp0 = (__half2*)&u0;
        __half2* hp1 = (__half2*)&u1;
#pragma unroll
        for (int j = 0; j < 4; j++) {
            hp0[j] = __floats2half2_rn(tile[c16 * 16 + 2 * j][yxl],
                                       tile[c16 * 16 + 2 * j + 1][yxl]);
            hp1[j] = __floats2half2_rn(tile[c16 * 16 + 8 + 2 * j][yxl],
                                       tile[c16 * 16 + 9 + 2 * j][yxl]);
        }
        size_t off = (size_t)(yx0 + yxl) * CPL + c16 * 16;
        *(uint4*)(dsth + off) = u0;
        *(uint4*)(dsth + off + 8) = u1;
    }
}

// ---------------- 1b) split off/wt weights; bvout ----------------
__global__ void convert_w(const float* __restrict__ Woff, const float* __restrict__ bo,
                          const float* __restrict__ Wwt, const float* __restrict__ bw,
                          const float* __restrict__ Wout, const float* __restrict__ bv) {
    int i = blockIdx.x * 256 + threadIdx.x;
    if (i < 32 * IND) {
        int n = i / IND, k = i - n * IND;
        float v = (n < 24) ? Woff[n * IND + k] : Wwt[(n - 24) * IND + k];
        __half h = __float2half_rn(v);
        g_Wow_hi[i] = h;
        g_Wow_lo[i] = __float2half_rn(v - __half2float(h));
    }
    if (i < 32) g_bow[i] = (i < 24) ? bo[i] : bw[i - 24];
    if (i < IND) {
        float s = 0.0f;
        for (int n = 0; n < IND; n++) s += Wout[i * IND + n] * bv[n];
        g_bvout[i] = s;
    }
}

// ---------------- 1c) W_comb = Wout @ Wv, split hi/lo ----------------
__global__ void make_wcomb(const float* __restrict__ Wout, const float* __restrict__ Wv) {
    __shared__ float wrow[IND];
    int m = blockIdx.x, k = threadIdx.x;
    wrow[k] = Wout[m * IND + k];
    __syncthreads();
    float s = 0.0f;
#pragma unroll 4
    for (int n = 0; n < IND; n++) s += wrow[n] * Wv[n * IND + k];
    __half h = __float2half_rn(s);
    g_Wc_hi[m * IND + k] = h;
    g_Wc_lo[m * IND + k] = __float2half_rn(s - __half2float(h));
}

// ---------------- bilinear corner weights ----------------
__device__ __forceinline__ void bilerp_setup(float u, float v, int& i00, int& i01,
                                             int& i10, int& i11, float& w00, float& w01,
                                             float& w10, float& w11) {
    float x = __saturatef(u) * 127.0f;
    float y = __saturatef(v) * 127.0f;
    float xf = floorf(x), yf = floorf(y);
    int ix0 = (int)xf, iy0 = (int)yf;
    int ix1 = min(ix0 + 1, 127), iy1 = min(iy0 + 1, 127);
    float wx = x - xf, wy = y - yf;
    w00 = (1.0f - wx) * (1.0f - wy);
    w01 = wx * (1.0f - wy);
    w10 = (1.0f - wx) * wy;
    w11 = wx * wy;
    i00 = iy0 * RESOL + ix0; i01 = iy0 * RESOL + ix1;
    i10 = iy1 * RESOL + ix0; i11 = iy1 * RESOL + ix1;
}

// ---------------- 2) sample features at query points (fp32 planes) ----------------
__global__ __launch_bounds__(256) void sample_query(const float* __restrict__ qp) {
    int gid = blockIdx.x * 256 + threadIdx.x;
    int pt = gid / 24, lane = gid - pt * 24;
    int c8 = lane * 8;
    int p = c8 >> 6, ch = c8 & 63;
    int b = pt >> 14;
    float px = qp[pt * 3 + 0], py = qp[pt * 3 + 1], pz = qp[pt * 3 + 2];
    float u = (p == 2) ? py : px;
    float v = (p == 1) ? py : pz;
    int i00, i01, i10, i11;
    float w00, w01, w10, w11;
    bilerp_setup(u, v, i00, i01, i10, i11, w00, w01, w10, w11);
    const float* base = g_planesf + (size_t)(b * 3 + p) * HWSZ * CPL + ch;
    float acc[8];
#pragma unroll
    for (int h = 0; h < 2; h++) {
        float4 f00 = *(const float4*)(base + (size_t)i00 * CPL + 4 * h);
        float4 f01 = *(const float4*)(base + (size_t)i01 * CPL + 4 * h);
        float4 f10 = *(const float4*)(base + (size_t)i10 * CPL + 4 * h);
        float4 f11 = *(const float4*)(base + (size_t)i11 * CPL + 4 * h);
        acc[4 * h + 0] = w00 * f00.x + w01 * f01.x + w10 * f10.x + w11 * f11.x;
        acc[4 * h + 1] = w00 * f00.y + w01 * f01.y + w10 * f10.y + w11 * f11.y;
        acc[4 * h + 2] = w00 * f00.z + w01 * f01.z + w10 * f10.z + w11 * f11.z;
        acc[4 * h + 3] = w00 * f00.w + w01 * f01.w + w10 * f10.w + w11 * f11.w;
    }
    float4* o = (float4*)(g_feat + (size_t)pt * IND + c8);
    o[0] = make_float4(acc[0], acc[1], acc[2], acc[3]);
    o[1] = make_float4(acc[4], acc[5], acc[6], acc[7]);
}

// ---------------- MMA helpers ----------------
__device__ __forceinline__ void mma16816(float* c, const unsigned* a, const unsigned* b) {
    asm volatile(
        "mma.sync.aligned.m16n8k16.row.col.f32.f16.f16.f32 "
        "{%0,%1,%2,%3}, {%4,%5,%6,%7}, {%8,%9}, {%0,%1,%2,%3};\n"
        : "+f"(c[0]), "+f"(c[1]), "+f"(c[2]), "+f"(c[3])
        : "r"(a[0]), "r"(a[1]), "r"(a[2]), "r"(a[3]), "r"(b[0]), "r"(b[1]));
}
__device__ __forceinline__ void split2(float2 v, unsigned& hi, unsigned& lo) {
    __half2 h = __floats2half2_rn(v.x, v.y);
    float2 hf = __half22float2(h);
    __half2 l = __floats2half2_rn(v.x - hf.x, v.y - hf.y);
    hi = *(unsigned*)&h;
    lo = *(unsigned*)&l;
}
__device__ __forceinline__ void load_a_raw(const float* p, float2* buf) {
    buf[0] = *(const float2*)(p);
    buf[1] = *(const float2*)(p + 8 * IND);
    buf[2] = *(const float2*)(p + 8);
    buf[3] = *(const float2*)(p + 8 * IND + 8);
}

// ---------------- 3) off+wt predictor via split-fp16 MMA (A double-buffered) -----
// M=NPTS, N=32, K=192. block 256 (8 warps x 32 rows), grid NPTS/256
__global__ __launch_bounds__(256) void predict_offwt_mma() {
    int tid = threadIdx.x, wid = tid >> 5, lane = tid & 31;
    int g = lane >> 2, t = lane & 3;
    int m_base = blockIdx.x * 256 + wid * 32;

    float c[2][4][4] = {};
    const float* Ap = g_feat + (size_t)(m_base + g) * IND + 2 * t;
    const __half* Bph = g_Wow_hi + (size_t)g * IND + 2 * t;
    const __half* Bpl = g_Wow_lo + (size_t)g * IND + 2 * t;

    float2 abuf[2][2][4];
    load_a_raw(Ap, abuf[0][0]);
    load_a_raw(Ap + 16 * IND, abuf[0][1]);

    for (int kt = 0; kt < 12; kt++) {
        int cur = kt & 1;
        if (kt < 11) {
            int k1 = (kt + 1) * 16;
            load_a_raw(Ap + k1, abuf[cur ^ 1][0]);
            load_a_raw(Ap + 16 * IND + k1, abuf[cur ^ 1][1]);
        }
        int k0 = kt * 16;
        unsigned ah[2][4], al[2][4], bh[4][2], bl[4][2];
#pragma unroll
        for (int ms = 0; ms < 2; ms++)
#pragma unroll
            for (int i = 0; i < 4; i++)
                split2(abuf[cur][ms][i], ah[ms][i], al[ms][i]);
#pragma unroll
        for (int ns = 0; ns < 4; ns++) {
            const __half* ph = Bph + (size_t)ns * 8 * IND + k0;
            const __half* pl = Bpl + (size_t)ns * 8 * IND + k0;
            bh[ns][0] = *(const unsigned*)ph;
            bh[ns][1] = *(const unsigned*)(ph + 8);
            bl[ns][0] = *(const unsigned*)pl;
            bl[ns][1] = *(const unsigned*)(pl + 8);
        }
#pragma unroll
        for (int ms = 0; ms < 2; ms++)
#pragma unroll
            for (int ns = 0; ns < 4; ns++) {
                mma16816(c[ms][ns], ah[ms], bh[ns]);
                mma16816(c[ms][ns], ah[ms], bl[ns]);
                mma16816(c[ms][ns], al[ms], bh[ns]);
            }
    }

#pragma unroll
    for (int ms = 0; ms < 2; ms++) {
        int r0 = m_base + ms * 16 + g;
        int r1 = r0 + 8;
#pragma unroll
        for (int ns = 0; ns < 4; ns++) {
            int nc = ns * 8 + 2 * t;
            float b0 = g_bow[nc], b1 = g_bow[nc + 1];
            *(float2*)(g_offwt + (size_t)r0 * 32 + nc) =
                make_float2(c[ms][ns][0] + b0, c[ms][ns][1] + b1);
            *(float2*)(g_offwt + (size_t)r1 * 32 + nc) =
                make_float2(c[ms][ns][2] + b0, c[ms][ns][3] + b1);
        }
    }
}

// ---------------- 4) sample offset points, weighted-accumulate (fp16 planes) -----
__global__ __launch_bounds__(256) void sample_aux(const float* __restrict__ qp) {
    int gid = blockIdx.x * 256 + threadIdx.x;
    int pt = gid / 24, lane = gid - pt * 24;
    int c8 = lane * 8;
    int p = c8 >> 6, ch = c8 & 63;
    int b = pt >> 14;
    float px = qp[pt * 3 + 0], py = qp[pt * 3 + 1], pz = qp[pt * 3 + 2];
    const float* ow = g_offwt + (size_t)pt * 32;
    const __half* base = g_planesh + (size_t)(b * 3 + p) * HWSZ * CPL + ch;
    float acc[8] = {};
    float wts = 0.0f;
#pragma unroll
    for (int s = 0; s < SSAMP; s++) {
        float qx = px + ow[s * 3 + 0];
        float qy = py + ow[s * 3 + 1];
        float qz = pz + ow[s * 3 + 2];
        float wgt = ow[24 + s];
        float u = (p == 2) ? qy : qx;
        float v = (p == 1) ? qy : qz;
        int i00, i01, i10, i11;
        float w00, w01, w10, w11;
        bilerp_setup(u, v, i00, i01, i10, i11, w00, w01, w10, w11);
        w00 *= wgt; w01 *= wgt; w10 *= wgt; w11 *= wgt;
        uint4 q00 = *(const uint4*)(base + (size_t)i00 * CPL);
        uint4 q01 = *(const uint4*)(base + (size_t)i01 * CPL);
        uint4 q10 = *(const uint4*)(base + (size_t)i10 * CPL);
        uint4 q11 = *(const uint4*)(base + (size_t)i11 * CPL);
        const __half2* h00 = (const __half2*)&q00;
        const __half2* h01 = (const __half2*)&q01;
        const __half2* h10 = (const __half2*)&q10;
        const __half2* h11 = (const __half2*)&q11;
#pragma unroll
        for (int i = 0; i < 4; i++) {
            float2 f00 = __half22float2(h00[i]);
            float2 f01 = __half22float2(h01[i]);
            float2 f10 = __half22float2(h10[i]);
            float2 f11 = __half22float2(h11[i]);
            acc[2 * i + 0] += w00 * f00.x + w01 * f01.x + w10 * f10.x + w11 * f11.x;
            acc[2 * i + 1] += w00 * f00.y + w01 * f01.y + w10 * f10.y + w11 * f11.y;
        }
        wts += wgt;
    }
    float4* o = (float4*)(g_auxw + (size_t)pt * IND + c8);
    o[0] = make_float4(acc[0], acc[1], acc[2], acc[3]);
    o[1] = make_float4(acc[4], acc[5], acc[6], acc[7]);
    if (lane == 0) g_wtsum[pt] = wts;
}

// ---------------- 5) fused GEMM: out = auxw@Wc^T + wts*bvout + bout + feat --------
// B tile staged in XOR-swizzled smem (conflict-free), A double-buffered from gmem.
// grid (NPTS/128, 3), block 256 (8 warps: 4m x 2n, warp tile 32x32)
__global__ __launch_bounds__(256) void gemm_comb(const float* __restrict__ bout,
                                                 float* __restrict__ outF) {
    __shared__ __half Bs[2][64 * IND];   // [hi/lo][n][k] 4B-word XOR swizzle
    int tid = threadIdx.x, wid = tid >> 5, lane = tid & 31;
    int g = lane >> 2, t = lane & 3;
    int m_base = blockIdx.x * 128 + (wid >> 1) * 32;
    int n_blk = blockIdx.y * 64;
    int nloc = (wid & 1) * 32;

    // stage B (hi/lo), uint4 stores with swizzle
    for (int idx = tid; idx < 64 * 24; idx += 256) {
        int n = idx / 24, c8 = idx - n * 24;
        int pw = (c8 * 4) ^ ((n & 7) << 2);
        int hoff = n * IND + (pw << 1);
        *(uint4*)(&Bs[0][hoff]) =
            *(const uint4*)(g_Wc_hi + (size_t)(n_blk + n) * IND + c8 * 8);
        *(uint4*)(&Bs[1][hoff]) =
            *(const uint4*)(g_Wc_lo + (size_t)(n_blk + n) * IND + c8 * 8);
    }
    __syncthreads();

    float c[2][4][4] = {};
    const float* Ap = g_auxw + (size_t)(m_base + g) * IND + 2 * t;

    float2 abuf[2][2][4];
    load_a_raw(Ap, abuf[0][0]);
    load_a_raw(Ap + 16 * IND, abuf[0][1]);

    for (int kt = 0; kt < 12; kt++) {
        int cur = kt & 1;
        if (kt < 11) {
            int k1 = (kt + 1) * 16;
            load_a_raw(Ap + k1, abuf[cur ^ 1][0]);
            load_a_raw(Ap + 16 * IND + k1, abuf[cur ^ 1][1]);
        }
        int k0 = kt * 16;
        unsigned ah[2][4], al[2][4], bh[4][2], bl[4][2];
#pragma unroll
        for (int ms = 0; ms < 2; ms++)
#pragma unroll
            for (int i = 0; i < 4; i++)
                split2(abuf[cur][ms][i], ah[ms][i], al[ms][i]);
        int w0 = (k0 >> 1) + t;
#pragma unroll
        for (int ns = 0; ns < 4; ns++) {
            int n = nloc + ns * 8 + g;
            int sw = (n & 7) << 2;
            int h0 = n * IND + ((w0 ^ sw) << 1);
            int h1 = n * IND + (((w0 + 4) ^ sw) << 1);
            bh[ns][0] = *(const unsigned*)(&Bs[0][h0]);
            bh[ns][1] = *(const unsigned*)(&Bs[0][h1]);
            bl[ns][0] = *(const unsigned*)(&Bs[1][h0]);
            bl[ns][1] = *(const unsigned*)(&Bs[1][h1]);
        }
#pragma unroll
        for (int ms = 0; ms < 2; ms++)
#pragma unroll
            for (int ns = 0; ns < 4; ns++) {
                mma16816(c[ms][ns], ah[ms], bh[ns]);
                mma16816(c[ms][ns], ah[ms], bl[ns]);
                mma16816(c[ms][ns], al[ms], bh[ns]);
            }
    }

    int n_base = n_blk + nloc;
#pragma unroll
    for (int ms = 0; ms < 2; ms++) {
        int r0 = m_base + ms * 16 + g;
        int r1 = r0 + 8;
        float rs0 = g_wtsum[r0], rs1 = g_wtsum[r1];
#pragma unroll
        for (int ns = 0; ns < 4; ns++) {
            int nc = n_base + ns * 8 + 2 * t;
            float bo0 = bout[nc], bo1 = bout[nc + 1];
            float bv0 = g_bvout[nc], bv1 = g_bvout[nc + 1];
            size_t o0 = (size_t)r0 * IND + nc;
            size_t o1 = (size_t)r1 * IND + nc;
            float2 f0 = *(const float2*)(g_feat + o0);
            float2 f1 = *(const float2*)(g_feat + o1);
            *(float2*)(outF + o0) = make_float2(
                c[ms][ns][0] + bv0 * rs0 + bo0 + f0.x,
                c[ms][ns][1] + bv1 * rs0 + bo1 + f0.y);
            *(float2*)(outF + o1) = make_float2(
                c[ms][ns][2] + bv0 * rs1 + bo0 + f1.x,
                c[ms][ns][3] + bv1 * rs1 + bo1 + f1.y);
        }
    }
}

// ---------------- launch ----------------
extern "C" void kernel_launch(void* const* d_in, const int* in_sizes, int n_in,
                              void* d_out, int out_size) {
    const float* qp    = (const float*)d_in[0];
    const float* fxz   = (const float*)d_in[1];
    const float* fxy   = (const float*)d_in[2];
    const float* fyz   = (const float*)d_in[3];
    const float* W_v   = (const float*)d_in[4];
    const float* b_v   = (const float*)d_in[5];
    const float* W_out = (const float*)d_in[6];
    const float* b_out = (const float*)d_in[7];
    const float* W_off = (const float*)d_in[8];
    const float* b_off = (const float*)d_in[9];
    const float* W_wt  = (const float*)d_in[10];
    const float* b_wt  = (const float*)d_in[11];
    float* out = (float*)d_out;

    transpose_planes<<<dim3(HWSZ / 128, BSZ, 3), 256>>>(fxz, fxy, fyz);
    convert_w<<<(32 * IND + 255) / 256, 256>>>(W_off, b_off, W_wt, b_wt, W_out, b_v);
    make_wcomb<<<IND, IND>>>(W_out, W_v);
    sample_query<<<NPTS * 24 / 256, 256>>>(qp);
    predict_offwt_mma<<<NPTS / 256, 256>>>();
    sample_aux<<<NPTS * 24 / 256, 256>>>(qp);
    gemm_comb<<<dim3(NPTS / 128, 3), 256>>>(b_out, out);
}

// round 8
// speedup vs baseline: 1.6591x; 1.0124x over previous
#include <cuda_runtime.h>
#include <cuda_fp16.h>

#define BSZ 4
#define NSQ 16384
#define SSAMP 8
#define CPL 64
#define RESOL 128
#define HWSZ (RESOL * RESOL)
#define IND 192
#define NPTS (BSZ * NSQ)   // 65536

// ---------------- scratch (static device globals; no allocation) ----------------
__device__ __align__(16) float  g_planesf[(size_t)BSZ * 3 * HWSZ * CPL]; // fp32 channel-last
__device__ __align__(16) __half g_planesh[(size_t)BSZ * 3 * HWSZ * CPL]; // fp16 channel-last
__device__ __align__(16) float  g_feat[(size_t)NPTS * IND];
__device__ __align__(16) float  g_offwt[(size_t)NPTS * 32];              // 24 off + 8 wt
__device__ __align__(16) float  g_auxw[(size_t)NPTS * IND];              // PERMUTED fragment order
__device__ float  g_wtsum[NPTS];
__device__ __align__(16) __half g_Wc_hi[IND * IND];                      // Wout@Wv split
__device__ __align__(16) __half g_Wc_lo[IND * IND];
__device__ float g_bvout[IND];                                           // Wout@b_v
__device__ __align__(16) __half g_Wow_hi[32 * IND];                      // [Woff;Wwt] packed
__device__ __align__(16) __half g_Wow_lo[32 * IND];
__device__ float g_bow[32];

// ---------------- 1) transpose planes to channel-last (fp32 + fp16) ----------------
// grid (HW/128, B, 3), block 256
__global__ __launch_bounds__(256) void transpose_planes(const float* __restrict__ pxz,
                                                        const float* __restrict__ pxy,
                                                        const float* __restrict__ pyz) {
    int p = blockIdx.z;
    int b = blockIdx.y;
    int yx0 = blockIdx.x * 128;
    const float* src = (p == 0 ? pxz : (p == 1 ? pxy : pyz)) + (size_t)b * CPL * HWSZ;
    float* dstf = g_planesf + (size_t)(b * 3 + p) * HWSZ * CPL;
    __half* dsth = g_planesh + (size_t)(b * 3 + p) * HWSZ * CPL;

    __shared__ float tile[CPL][132];
    int t = threadIdx.x;
    int tx = t & 31, ty = t >> 5;
#pragma unroll
    for (int cb = 0; cb < CPL; cb += 8) {
        int c = cb + ty;
        float4 v = *(const float4*)(src + (size_t)c * HWSZ + yx0 + tx * 4);
        *(float4*)(&tile[c][tx * 4]) = v;
    }
    __syncthreads();
#pragma unroll
    for (int i = 0; i < 4; i++) {
        int e = i * 256 + t;
        int c8 = e >> 7, yxl = e & 127;
        float v[8];
#pragma unroll
        for (int j = 0; j < 8; j++) v[j] = tile[c8 * 8 + j][yxl];
        size_t off = (size_t)(yx0 + yxl) * CPL + c8 * 8;
        *(float4*)(dstf + off) = make_float4(v[0], v[1], v[2], v[3]);
        *(float4*)(dstf + off + 4) = make_float4(v[4], v[5], v[6], v[7]);
    }
#pragma unroll
    for (int i = 0; i < 2; i++) {
        int e = i * 256 + t;
        int c16 = e >> 7, yxl = e & 127;
        uint4 u0, u1;
        __half2* hp0 = (__half2*)&u0;
        __half2* hp1 = (__half2*)&u1;
#pragma unroll
        for (int j = 0; j < 4; j++) {
            hp0[j] = __floats2half2_rn(tile[c16 * 16 + 2 * j][yxl],
                                       tile[c16 * 16 + 2 * j + 1][yxl]);
            hp1[j] = __floats2half2_rn(tile[c16 * 16 + 8 + 2 * j][yxl],
                                       tile[c16 * 16 + 9 + 2 * j][yxl]);
        }
        size_t off = (size_t)(yx0 + yxl) * CPL + c16 * 16;
        *(uint4*)(dsth + off) = u0;
        *(uint4*)(dsth + off + 8) = u1;
    }
}

// ---------------- 1b) split off/wt weights; bvout ----------------
__global__ void convert_w(const float* __restrict__ Woff, const float* __restrict__ bo,
                          const float* __restrict__ Wwt, const float* __restrict__ bw,
                          const float* __restrict__ Wout, const float* __restrict__ bv) {
    int i = blockIdx.x * 256 + threadIdx.x;
    if (i < 32 * IND) {
        int n = i / IND, k = i - n * IND;
        float v = (n < 24) ? Woff[n * IND + k] : Wwt[(n - 24) * IND + k];
        __half h = __float2half_rn(v);
        g_Wow_hi[i] = h;
        g_Wow_lo[i] = __float2half_rn(v - __half2float(h));
    }
    if (i < 32) g_bow[i] = (i < 24) ? bo[i] : bw[i - 24];
    if (i < IND) {
        float s = 0.0f;
        for (int n = 0; n < IND; n++) s += Wout[i * IND + n] * bv[n];
        g_bvout[i] = s;
    }
}

// ---------------- 1c) W_comb = Wout @ Wv, split hi/lo ----------------
__global__ void make_wcomb(const float* __restrict__ Wout, const float* __restrict__ Wv) {
    __shared__ float wrow[IND];
    int m = blockIdx.x, k = threadIdx.x;
    wrow[k] = Wout[m * IND + k];
    __syncthreads();
    float s = 0.0f;
#pragma unroll 4
    for (int n = 0; n < IND; n++) s += wrow[n] * Wv[n * IND + k];
    __half h = __float2half_rn(s);
    g_Wc_hi[m * IND + k] = h;
    g_Wc_lo[m * IND + k] = __float2half_rn(s - __half2float(h));
}

// ---------------- bilinear corner weights ----------------
__device__ __forceinline__ void bilerp_setup(float u, float v, int& i00, int& i01,
                                             int& i10, int& i11, float& w00, float& w01,
                                             float& w10, float& w11) {
    float x = __saturatef(u) * 127.0f;
    float y = __saturatef(v) * 127.0f;
    float xf = floorf(x), yf = floorf(y);
    int ix0 = (int)xf, iy0 = (int)yf;
    int ix1 = min(ix0 + 1, 127), iy1 = min(iy0 + 1, 127);
    float wx = x - xf, wy = y - yf;
    w00 = (1.0f - wx) * (1.0f - wy);
    w01 = wx * (1.0f - wy);
    w10 = (1.0f - wx) * wy;
    w11 = wx * wy;
    i00 = iy0 * RESOL + ix0; i01 = iy0 * RESOL + ix1;
    i10 = iy1 * RESOL + ix0; i11 = iy1 * RESOL + ix1;
}

// ---------------- 2) sample features at query points (fp32 planes) ----------------
__global__ __launch_bounds__(256) void sample_query(const float* __restrict__ qp) {
    int gid = blockIdx.x * 256 + threadIdx.x;
    int pt = gid / 24, lane = gid - pt * 24;
    int c8 = lane * 8;
    int p = c8 >> 6, ch = c8 & 63;
    int b = pt >> 14;
    float px = qp[pt * 3 + 0], py = qp[pt * 3 + 1], pz = qp[pt * 3 + 2];
    float u = (p == 2) ? py : px;
    float v = (p == 1) ? py : pz;
    int i00, i01, i10, i11;
    float w00, w01, w10, w11;
    bilerp_setup(u, v, i00, i01, i10, i11, w00, w01, w10, w11);
    const float* base = g_planesf + (size_t)(b * 3 + p) * HWSZ * CPL + ch;
    float acc[8];
#pragma unroll
    for (int h = 0; h < 2; h++) {
        float4 f00 = *(const float4*)(base + (size_t)i00 * CPL + 4 * h);
        float4 f01 = *(const float4*)(base + (size_t)i01 * CPL + 4 * h);
        float4 f10 = *(const float4*)(base + (size_t)i10 * CPL + 4 * h);
        float4 f11 = *(const float4*)(base + (size_t)i11 * CPL + 4 * h);
        acc[4 * h + 0] = w00 * f00.x + w01 * f01.x + w10 * f10.x + w11 * f11.x;
        acc[4 * h + 1] = w00 * f00.y + w01 * f01.y + w10 * f10.y + w11 * f11.y;
        acc[4 * h + 2] = w00 * f00.z + w01 * f01.z + w10 * f10.z + w11 * f11.z;
        acc[4 * h + 3] = w00 * f00.w + w01 * f01.w + w10 * f10.w + w11 * f11.w;
    }
    float4* o = (float4*)(g_feat + (size_t)pt * IND + c8);
    o[0] = make_float4(acc[0], acc[1], acc[2], acc[3]);
    o[1] = make_float4(acc[4], acc[5], acc[6], acc[7]);
}

// ---------------- MMA helpers ----------------
__device__ __forceinline__ void mma16816(float* c, const unsigned* a, const unsigned* b) {
    asm volatile(
        "mma.sync.aligned.m16n8k16.row.col.f32.f16.f16.f32 "
        "{%0,%1,%2,%3}, {%4,%5,%6,%7}, {%8,%9}, {%0,%1,%2,%3};\n"
        : "+f"(c[0]), "+f"(c[1]), "+f"(c[2]), "+f"(c[3])
        : "r"(a[0]), "r"(a[1]), "r"(a[2]), "r"(a[3]), "r"(b[0]), "r"(b[1]));
}
__device__ __forceinline__ void split2(float2 v, unsigned& hi, unsigned& lo) {
    __half2 h = __floats2half2_rn(v.x, v.y);
    float2 hf = __half22float2(h);
    __half2 l = __floats2half2_rn(v.x - hf.x, v.y - hf.y);
    hi = *(unsigned*)&h;
    lo = *(unsigned*)&l;
}
__device__ __forceinline__ void load_a_raw(const float* p, float2* buf) {
    buf[0] = *(const float2*)(p);
    buf[1] = *(const float2*)(p + 8 * IND);
    buf[2] = *(const float2*)(p + 8);
    buf[3] = *(const float2*)(p + 8 * IND + 8);
}
// permuted A: one float4 per row holds frag pairs {2t,2t+1,2t+8,2t+9}
__device__ __forceinline__ void load_a_perm(const float* p, float2* buf) {
    float4 v0 = *(const float4*)(p);
    float4 v1 = *(const float4*)(p + 8 * IND);
    buf[0] = make_float2(v0.x, v0.y);
    buf[1] = make_float2(v1.x, v1.y);
    buf[2] = make_float2(v0.z, v0.w);
    buf[3] = make_float2(v1.z, v1.w);
}

// ---------------- 3) off+wt predictor via split-fp16 MMA (A double-buffered) -----
__global__ __launch_bounds__(256) void predict_offwt_mma() {
    int tid = threadIdx.x, wid = tid >> 5, lane = tid & 31;
    int g = lane >> 2, t = lane & 3;
    int m_base = blockIdx.x * 256 + wid * 32;

    float c[2][4][4] = {};
    const float* Ap = g_feat + (size_t)(m_base + g) * IND + 2 * t;
    const __half* Bph = g_Wow_hi + (size_t)g * IND + 2 * t;
    const __half* Bpl = g_Wow_lo + (size_t)g * IND + 2 * t;

    float2 abuf[2][2][4];
    load_a_raw(Ap, abuf[0][0]);
    load_a_raw(Ap + 16 * IND, abuf[0][1]);

    for (int kt = 0; kt < 12; kt++) {
        int cur = kt & 1;
        if (kt < 11) {
            int k1 = (kt + 1) * 16;
            load_a_raw(Ap + k1, abuf[cur ^ 1][0]);
            load_a_raw(Ap + 16 * IND + k1, abuf[cur ^ 1][1]);
        }
        int k0 = kt * 16;
        unsigned ah[2][4], al[2][4], bh[4][2], bl[4][2];
#pragma unroll
        for (int ms = 0; ms < 2; ms++)
#pragma unroll
            for (int i = 0; i < 4; i++)
                split2(abuf[cur][ms][i], ah[ms][i], al[ms][i]);
#pragma unroll
        for (int ns = 0; ns < 4; ns++) {
            const __half* ph = Bph + (size_t)ns * 8 * IND + k0;
            const __half* pl = Bpl + (size_t)ns * 8 * IND + k0;
            bh[ns][0] = *(const unsigned*)ph;
            bh[ns][1] = *(const unsigned*)(ph + 8);
            bl[ns][0] = *(const unsigned*)pl;
            bl[ns][1] = *(const unsigned*)(pl + 8);
        }
#pragma unroll
        for (int ms = 0; ms < 2; ms++)
#pragma unroll
            for (int ns = 0; ns < 4; ns++) {
                mma16816(c[ms][ns], ah[ms], bh[ns]);
                mma16816(c[ms][ns], ah[ms], bl[ns]);
                mma16816(c[ms][ns], al[ms], bh[ns]);
            }
    }

#pragma unroll
    for (int ms = 0; ms < 2; ms++) {
        int r0 = m_base + ms * 16 + g;
        int r1 = r0 + 8;
#pragma unroll
        for (int ns = 0; ns < 4; ns++) {
            int nc = ns * 8 + 2 * t;
            float b0 = g_bow[nc], b1 = g_bow[nc + 1];
            *(float2*)(g_offwt + (size_t)r0 * 32 + nc) =
                make_float2(c[ms][ns][0] + b0, c[ms][ns][1] + b1);
            *(float2*)(g_offwt + (size_t)r1 * 32 + nc) =
                make_float2(c[ms][ns][2] + b0, c[ms][ns][3] + b1);
        }
    }
}

// ---------------- 4) sample offset points, weighted-accumulate (fp16 planes) -----
// writes g_auxw in PERMUTED fragment order
__global__ __launch_bounds__(256) void sample_aux(const float* __restrict__ qp) {
    int gid = blockIdx.x * 256 + threadIdx.x;
    int pt = gid / 24, lane = gid - pt * 24;
    int c8 = lane * 8;
    int p = c8 >> 6, ch = c8 & 63;
    int b = pt >> 14;
    float px = qp[pt * 3 + 0], py = qp[pt * 3 + 1], pz = qp[pt * 3 + 2];

    // vectorized offwt: 8 x LDG.128 into unrolled register array
    float owl[32];
    {
        const float4* ow4 = (const float4*)(g_offwt + (size_t)pt * 32);
#pragma unroll
        for (int i = 0; i < 8; i++) {
            float4 v = ow4[i];
            owl[4 * i + 0] = v.x; owl[4 * i + 1] = v.y;
            owl[4 * i + 2] = v.z; owl[4 * i + 3] = v.w;
        }
    }

    const __half* base = g_planesh + (size_t)(b * 3 + p) * HWSZ * CPL + ch;
    float acc[8] = {};
    float wts = 0.0f;
#pragma unroll
    for (int s = 0; s < SSAMP; s++) {
        float qx = px + owl[s * 3 + 0];
        float qy = py + owl[s * 3 + 1];
        float qz = pz + owl[s * 3 + 2];
        float wgt = owl[24 + s];
        float u = (p == 2) ? qy : qx;
        float v = (p == 1) ? qy : qz;
        int i00, i01, i10, i11;
        float w00, w01, w10, w11;
        bilerp_setup(u, v, i00, i01, i10, i11, w00, w01, w10, w11);
        w00 *= wgt; w01 *= wgt; w10 *= wgt; w11 *= wgt;
        uint4 q00 = *(const uint4*)(base + (size_t)i00 * CPL);
        uint4 q01 = *(const uint4*)(base + (size_t)i01 * CPL);
        uint4 q10 = *(const uint4*)(base + (size_t)i10 * CPL);
        uint4 q11 = *(const uint4*)(base + (size_t)i11 * CPL);
        const __half2* h00 = (const __half2*)&q00;
        const __half2* h01 = (const __half2*)&q01;
        const __half2* h10 = (const __half2*)&q10;
        const __half2* h11 = (const __half2*)&q11;
#pragma unroll
        for (int i = 0; i < 4; i++) {
            float2 f00 = __half22float2(h00[i]);
            float2 f01 = __half22float2(h01[i]);
            float2 f10 = __half22float2(h10[i]);
            float2 f11 = __half22float2(h11[i]);
            acc[2 * i + 0] += w00 * f00.x + w01 * f01.x + w10 * f10.x + w11 * f11.x;
            acc[2 * i + 1] += w00 * f00.y + w01 * f01.y + w10 * f10.y + w11 * f11.y;
        }
        wts += wgt;
    }
    // permuted store: 16-block base + {0,4,8,12} (+2 for upper half)
    {
        int blk = c8 & ~15;
        int half = (c8 & 8) ? 2 : 0;
        float* o = g_auxw + (size_t)pt * IND + blk + half;
#pragma unroll
        for (int i = 0; i < 4; i++)
            *(float2*)(o + 4 * i) = make_float2(acc[2 * i], acc[2 * i + 1]);
    }
    if (lane == 0) g_wtsum[pt] = wts;
}

// ---------------- 5) fused GEMM: out = auxw@Wc^T + wts*bvout + bout + feat --------
// A read from permuted g_auxw (one float4 per row per kt), B in swizzled smem.
__global__ __launch_bounds__(256) void gemm_comb(const float* __restrict__ bout,
                                                 float* __restrict__ outF) {
    __shared__ __half Bs[2][64 * IND];
    int tid = threadIdx.x, wid = tid >> 5, lane = tid & 31;
    int g = lane >> 2, t = lane & 3;
    int m_base = blockIdx.x * 128 + (wid >> 1) * 32;
    int n_blk = blockIdx.y * 64;
    int nloc = (wid & 1) * 32;

    for (int idx = tid; idx < 64 * 24; idx += 256) {
        int n = idx / 24, c8 = idx - n * 24;
        int pw = (c8 * 4) ^ ((n & 7) << 2);
        int hoff = n * IND + (pw << 1);
        *(uint4*)(&Bs[0][hoff]) =
            *(const uint4*)(g_Wc_hi + (size_t)(n_blk + n) * IND + c8 * 8);
        *(uint4*)(&Bs[1][hoff]) =
            *(const uint4*)(g_Wc_lo + (size_t)(n_blk + n) * IND + c8 * 8);
    }
    __syncthreads();

    float c[2][4][4] = {};
    const float* Ap = g_auxw + (size_t)(m_base + g) * IND + 4 * t;

    float2 abuf[2][2][4];
    load_a_perm(Ap, abuf[0][0]);
    load_a_perm(Ap + 16 * IND, abuf[0][1]);

    for (int kt = 0; kt < 12; kt++) {
        int cur = kt & 1;
        if (kt < 11) {
            int k1 = (kt + 1) * 16;
            load_a_perm(Ap + k1, abuf[cur ^ 1][0]);
            load_a_perm(Ap + 16 * IND + k1, abuf[cur ^ 1][1]);
        }
        int k0 = kt * 16;
        unsigned ah[2][4], al[2][4], bh[4][2], bl[4][2];
#pragma unroll
        for (int ms = 0; ms < 2; ms++)
#pragma unroll
            for (int i = 0; i < 4; i++)
                split2(abuf[cur][ms][i], ah[ms][i], al[ms][i]);
        int w0 = (k0 >> 1) + t;
#pragma unroll
        for (int ns = 0; ns < 4; ns++) {
            int n = nloc + ns * 8 + g;
            int sw = (n & 7) << 2;
            int h0 = n * IND + ((w0 ^ sw) << 1);
            int h1 = n * IND + (((w0 + 4) ^ sw) << 1);
            bh[ns][0] = *(const unsigned*)(&Bs[0][h0]);
            bh[ns][1] = *(const unsigned*)(&Bs[0][h1]);
            bl[ns][0] = *(const unsigned*)(&Bs[1][h0]);
            bl[ns][1] = *(const unsigned*)(&Bs[1][h1]);
        }
#pragma unroll
        for (int ms = 0; ms < 2; ms++)
#pragma unroll
            for (int ns = 0; ns < 4; ns++) {
                mma16816(c[ms][ns], ah[ms], bh[ns]);
                mma16816(c[ms][ns], ah[ms], bl[ns]);
                mma16816(c[ms][ns], al[ms], bh[ns]);
            }
    }

    int n_base = n_blk + nloc;
#pragma unroll
    for (int ms = 0; ms < 2; ms++) {
        int r0 = m_base + ms * 16 + g;
        int r1 = r0 + 8;
        float rs0 = g_wtsum[r0], rs1 = g_wtsum[r1];
#pragma unroll
        for (int ns = 0; ns < 4; ns++) {
            int nc = n_base + ns * 8 + 2 * t;
            float bo0 = bout[nc], bo1 = bout[nc + 1];
            float bv0 = g_bvout[nc], bv1 = g_bvout[nc + 1];
            size_t o0 = (size_t)r0 * IND + nc;
            size_t o1 = (size_t)r1 * IND + nc;
            float2 f0 = *(const float2*)(g_feat + o0);
            float2 f1 = *(const float2*)(g_feat + o1);
            *(float2*)(outF + o0) = make_float2(
                c[ms][ns][0] + bv0 * rs0 + bo0 + f0.x,
                c[ms][ns][1] + bv1 * rs0 + bo1 + f0.y);
            *(float2*)(outF + o1) = make_float2(
                c[ms][ns][2] + bv0 * rs1 + bo0 + f1.x,
                c[ms][ns][3] + bv1 * rs1 + bo1 + f1.y);
        }
    }
}

// ---------------- launch ----------------
extern "C" void kernel_launch(void* const* d_in, const int* in_sizes, int n_in,
                              void* d_out, int out_size) {
    const float* qp    = (const float*)d_in[0];
    const float* fxz   = (const float*)d_in[1];
    const float* fxy   = (const float*)d_in[2];
    const float* fyz   = (const float*)d_in[3];
    const float* W_v   = (const float*)d_in[4];
    const float* b_v   = (const float*)d_in[5];
    const float* W_out = (const float*)d_in[6];
    const float* b_out = (const float*)d_in[7];
    const float* W_off = (const float*)d_in[8];
    const float* b_off = (const float*)d_in[9];
    const float* W_wt  = (const float*)d_in[10];
    const float* b_wt  = (const float*)d_in[11];
    float* out = (float*)d_out;

    transpose_planes<<<dim3(HWSZ / 128, BSZ, 3), 256>>>(fxz, fxy, fyz);
    convert_w<<<(32 * IND + 255) / 256, 256>>>(W_off, b_off, W_wt, b_wt, W_out, b_v);
    make_wcomb<<<IND, IND>>>(W_out, W_v);
    sample_query<<<NPTS * 24 / 256, 256>>>(qp);
    predict_offwt_mma<<<NPTS / 256, 256>>>();
    sample_aux<<<NPTS * 24 / 256, 256>>>(qp);
    gemm_comb<<<dim3(NPTS / 128, 3), 256>>>(b_out, out);
}